// round 11
// baseline (speedup 1.0000x reference)
#include <cuda_runtime.h>
#include <cuda_bf16.h>
#include <math.h>
#include <stdint.h>

#define BT_N 64
#define LQ   256
#define LK   512
#define CDIM 512
#define NH   8
#define HD   64

typedef __nv_bfloat16 bf16;

// ---- device scratch ----
__device__ bf16 g_qbf [(size_t)16384 * 512];
__device__ bf16 g_kvbf[(size_t)32768 * 512];
__device__ bf16 g_wq  [512 * 512];
__device__ bf16 g_wkv [1024 * 512];
__device__ bf16 g_wm  [512 * 512];
__device__ bf16 g_qh  [(size_t)BT_N * NH * LQ * HD];
__device__ bf16 g_kh  [(size_t)BT_N * NH * LK * HD];
__device__ bf16 g_vh  [(size_t)BT_N * NH * LK * HD];   // V row-major: [bt][h][lk][d]
__device__ bf16 g_xm  [(size_t)BT_N * LQ * CDIM];

// ---------------------------------------------------------------------------
__device__ __forceinline__ unsigned pk(float lo, float hi) {
    unsigned r;
    asm("cvt.rn.bf16x2.f32 %0, %1, %2;" : "=r"(r) : "f"(hi), "f"(lo));
    return r;
}
__device__ __forceinline__ uint32_t smem_u32(const void* p) {
    uint32_t a;
    asm("{ .reg .u64 t; cvta.to.shared.u64 t, %1; cvt.u32.u64 %0, t; }" : "=r"(a) : "l"(p));
    return a;
}
__device__ __forceinline__ void cp_async16(uint32_t dst, const void* src) {
    asm volatile("cp.async.cg.shared.global [%0], [%1], 16;" :: "r"(dst), "l"(src));
}
__device__ __forceinline__ void cp_commit() { asm volatile("cp.async.commit_group;" ::: "memory"); }
template<int N> __device__ __forceinline__ void cp_wait() { asm volatile("cp.async.wait_group %0;" :: "n"(N) : "memory"); }

__device__ __forceinline__ void ldm_x4(unsigned* r, uint32_t addr) {
    asm volatile("ldmatrix.sync.aligned.m8n8.x4.shared.b16 {%0,%1,%2,%3}, [%4];"
                 : "=r"(r[0]), "=r"(r[1]), "=r"(r[2]), "=r"(r[3]) : "r"(addr));
}
__device__ __forceinline__ void ldm_x4_t(unsigned* r, uint32_t addr) {
    asm volatile("ldmatrix.sync.aligned.m8n8.x4.trans.shared.b16 {%0,%1,%2,%3}, [%4];"
                 : "=r"(r[0]), "=r"(r[1]), "=r"(r[2]), "=r"(r[3]) : "r"(addr));
}

__device__ __forceinline__ void mma16816(float* d, const unsigned* a, unsigned b0, unsigned b1) {
    asm volatile(
        "mma.sync.aligned.m16n8k16.row.col.f32.bf16.bf16.f32 "
        "{%0,%1,%2,%3},{%4,%5,%6,%7},{%8,%9},{%0,%1,%2,%3};"
        : "+f"(d[0]), "+f"(d[1]), "+f"(d[2]), "+f"(d[3])
        : "r"(a[0]), "r"(a[1]), "r"(a[2]), "r"(a[3]), "r"(b0), "r"(b1));
}

// ---------------------------------------------------------------------------
// fp32 -> bf16 conversion: single merged kernel (unit = 8 elements)
// ---------------------------------------------------------------------------
#define Q8   (16384 * 512 / 8)
#define KV8  (32768 * 512 / 8)
#define WQ8  (512 * 512 / 8)
#define WKV8 (1024 * 512 / 8)
#define WM8  (512 * 512 / 8)
#define ALL8 (Q8 + KV8 + WQ8 + WKV8 + WM8)

__device__ __forceinline__ void conv8(const float* src, bf16* dst, int i) {
    const float4 a = ((const float4*)src)[2 * i];
    const float4 b = ((const float4*)src)[2 * i + 1];
    ((uint4*)dst)[i] = make_uint4(pk(a.x, a.y), pk(a.z, a.w), pk(b.x, b.y), pk(b.z, b.w));
}

__global__ __launch_bounds__(256)
void convert_all(const float* __restrict__ q, const float* __restrict__ kv,
                 const float* __restrict__ wq, const float* __restrict__ wkv,
                 const float* __restrict__ wm) {
    int i = blockIdx.x * blockDim.x + threadIdx.x;
    if (i < Q8)                          conv8(q,   g_qbf,  i);
    else if (i < Q8 + KV8)               conv8(kv,  g_kvbf, i - Q8);
    else if (i < Q8 + KV8 + WQ8)         conv8(wq,  g_wq,   i - Q8 - KV8);
    else if (i < Q8 + KV8 + WQ8 + WKV8)  conv8(wkv, g_wkv,  i - Q8 - KV8 - WQ8);
    else                                 conv8(wm,  g_wm,   i - Q8 - KV8 - WQ8 - WKV8);
}

// ---------------------------------------------------------------------------
// Merged projection GEMM (Q proj + KV proj in one launch).
// CTA tile 128x256, BK=64, 512 threads = 16 warps (2M x 8N), warp 64x32.
// Stage = A(128*144) + B(256*144) = 55296 B; 3 stages = 165888 B -> 1 CTA/SM
// (16 warps/SM). Blocks [0,256): Q proj; [256,1280): KV proj.
// Epilogue: +bias, per-64-chunk L2 normalize -> g_qh / g_kh / g_vh.
// ---------------------------------------------------------------------------
#define PSTAGE 55296
#define PSMEM  (3 * PSTAGE)

__global__ __launch_bounds__(512, 1)
void proj_gemm(const float* __restrict__ bq, const float* __restrict__ bkv)
{
    extern __shared__ bf16 dsm[];
    __shared__ float sred[1024];
    const uint32_t smBase = smem_u32(dsm);

    const int tid   = threadIdx.x;
    const int lane  = tid & 31;
    const int wid   = tid >> 5;        // 0..15
    const int warpM = wid >> 3;        // 0..1
    const int warpN = wid & 7;         // 0..7
    const int g     = lane >> 2;
    const int t2    = (lane & 3) * 2;
    const int lr    = lane & 15;
    const int lc    = lane >> 4;

    const bool isQ = blockIdx.x < 256;
    int bm, bn;
    const bf16 *A, *W;
    const float* bias;
    if (isQ) {
        int b = blockIdx.x;
        bn = (b & 1) * 256;  bm = (b >> 1) * 128;
        A = g_qbf;  W = g_wq;  bias = bq;
    } else {
        int b = blockIdx.x - 256;
        bn = (b & 3) * 256;  bm = (b >> 2) * 128;
        A = g_kvbf; W = g_wkv; bias = bkv;
    }

    // loader: A 128x64 (2 chunks/thread), B 256x64 (4 chunks/thread)
    const int lrow = tid >> 3;         // 0..63
    const int lcc  = tid & 7;
    const bf16* srcA[2];
    const bf16* srcB[4];
    uint32_t dstA[2], dstB[4];
    #pragma unroll
    for (int it = 0; it < 2; it++) {
        int row = lrow + it * 64;
        srcA[it] = A + (size_t)(bm + row) * CDIM + lcc * 8;
        dstA[it] = (uint32_t)(row * 144 + lcc * 16);
    }
    #pragma unroll
    for (int it = 0; it < 4; it++) {
        int row = lrow + it * 64;
        srcB[it] = W + (size_t)(bn + row) * CDIM + lcc * 8;
        dstB[it] = (uint32_t)(18432 + row * 144 + lcc * 16);
    }

    const uint32_t aoff = (uint32_t)((warpM * 64 + lr) * 144 + lc * 16);
    const uint32_t boff = (uint32_t)(18432 + (warpN * 32 + lr) * 144 + lc * 16);

    auto load_tile = [&](int t, int stage) {
        const uint32_t st = smBase + stage * PSTAGE;
        const int koff = t * 64;
        #pragma unroll
        for (int it = 0; it < 2; it++)
            cp_async16(st + dstA[it], srcA[it] + koff);
        #pragma unroll
        for (int it = 0; it < 4; it++)
            cp_async16(st + dstB[it], srcB[it] + koff);
    };

    float acc[4][4][4] = {};

    load_tile(0, 0); cp_commit();
    load_tile(1, 1); cp_commit();

    #pragma unroll
    for (int t = 0; t < 8; t++) {
        cp_wait<1>();
        __syncthreads();
        if (t + 2 < 8) load_tile(t + 2, (t + 2) % 3);
        cp_commit();

        const uint32_t sa = smBase + (t % 3) * PSTAGE;
        #pragma unroll
        for (int ks = 0; ks < 4; ks++) {
            const int ko2 = ks * 32;
            unsigned af[4][4], bfm[2][4];
            #pragma unroll
            for (int ma = 0; ma < 4; ma++)
                ldm_x4(af[ma], sa + aoff + ma * 16 * 144 + ko2);
            #pragma unroll
            for (int p = 0; p < 2; p++)
                ldm_x4(bfm[p], sa + boff + p * 16 * 144 + ko2);
            #pragma unroll
            for (int ma = 0; ma < 4; ma++)
                #pragma unroll
                for (int nb = 0; nb < 4; nb++)
                    mma16816(acc[ma][nb], af[ma],
                             bfm[nb >> 1][nb & 1], bfm[nb >> 1][2 + (nb & 1)]);
        }
    }

    // bias add
    float2 bv[4];
    #pragma unroll
    for (int nb = 0; nb < 4; nb++)
        bv[nb] = *(const float2*)&bias[bn + warpN * 32 + nb * 8 + t2];
    #pragma unroll
    for (int ma = 0; ma < 4; ma++)
        #pragma unroll
        for (int nb = 0; nb < 4; nb++) {
            acc[ma][nb][0] += bv[nb].x; acc[ma][nb][1] += bv[nb].y;
            acc[ma][nb][2] += bv[nb].x; acc[ma][nb][3] += bv[nb].y;
        }

    // per-row sum of squares over the warp's 32 cols, then pair warps
    float ssq[4][2];
    #pragma unroll
    for (int ma = 0; ma < 4; ma++)
        #pragma unroll
        for (int h2 = 0; h2 < 2; h2++) {
            float s = 0.f;
            #pragma unroll
            for (int nb = 0; nb < 4; nb++) {
                float x = acc[ma][nb][h2 * 2], y = acc[ma][nb][h2 * 2 + 1];
                s += x * x + y * y;
            }
            s += __shfl_xor_sync(0xffffffffu, s, 1);
            s += __shfl_xor_sync(0xffffffffu, s, 2);
            ssq[ma][h2] = s;
        }
    __syncthreads();
    if ((lane & 3) == 0) {
        #pragma unroll
        for (int ma = 0; ma < 4; ma++)
            #pragma unroll
            for (int h2 = 0; h2 < 2; h2++)
                sred[wid * 64 + ma * 16 + h2 * 8 + g] = ssq[ma][h2];
    }
    __syncthreads();
    #pragma unroll
    for (int ma = 0; ma < 4; ma++)
        #pragma unroll
        for (int h2 = 0; h2 < 2; h2++) {
            int r = ma * 16 + h2 * 8 + g;
            float tot = sred[(wid & ~1) * 64 + r] + sred[((wid & ~1) + 1) * 64 + r];
            float rn = 1.f / fmaxf(sqrtf(tot), 1e-12f);
            int m = bm + warpM * 64 + r;
            #pragma unroll
            for (int nb = 0; nb < 4; nb++) {
                int n = bn + warpN * 32 + nb * 8 + t2;
                float v0 = acc[ma][nb][h2 * 2] * rn;
                float v1 = acc[ma][nb][h2 * 2 + 1] * rn;
                if (isQ) {
                    int bt = m >> 8, lq = m & 255;
                    int h = n >> 6, d = n & 63;
                    *(unsigned*)&g_qh[(((size_t)(bt * 8 + h)) * 256 + lq) * 64 + d] = pk(v0, v1);
                } else {
                    int bt = m >> 9, lk = m & 511;
                    int h = (n >> 6) & 7, d = n & 63;
                    bf16* base = (n < 512) ? g_kh : g_vh;
                    *(unsigned*)&base[(((size_t)(bt * 8 + h)) * 512 + lk) * 64 + d] = pk(v0, v1);
                }
            }
        }
}

// ---------------------------------------------------------------------------
// Output GEMM (xm @ Wm^T + bias + shortcut), R7 proven config:
// CTA 128x128, BK=64, 256 threads (8 warps 2Mx4N), 3-stage cp.async.
// ---------------------------------------------------------------------------
#define GSTAGE 36864
#define GSMEM  (3 * GSTAGE)

__global__ __launch_bounds__(256, 2)
void out_gemm(const float* __restrict__ bias,
              const float* __restrict__ shortcut,
              float* __restrict__ out)
{
    extern __shared__ bf16 dsm[];
    const uint32_t smBase = smem_u32(dsm);

    const int tid   = threadIdx.x;
    const int lane  = tid & 31;
    const int wid   = tid >> 5;
    const int warpM = wid >> 2;
    const int warpN = wid & 3;
    const int g     = lane >> 2;
    const int t2    = (lane & 3) * 2;
    const int lr    = lane & 15;
    const int lc    = lane >> 4;
    const int bm    = blockIdx.y * 128;
    const int bn    = blockIdx.x * 128;

    const bf16* A = g_xm;
    const bf16* W = g_wm;

    const int lrow = tid >> 3;
    const int lcc  = tid & 7;
    const bf16* srcA[4];
    const bf16* srcB[4];
    uint32_t dstOff[4];
    #pragma unroll
    for (int it = 0; it < 4; it++) {
        int row = lrow + it * 32;
        srcA[it] = A + (size_t)(bm + row) * CDIM + lcc * 8;
        srcB[it] = W + (size_t)(bn + row) * CDIM + lcc * 8;
        dstOff[it] = (uint32_t)(row * 144 + lcc * 16);
    }

    const uint32_t aoff = (uint32_t)((warpM * 64 + lr) * 144 + lc * 16);
    const uint32_t boff = (uint32_t)((warpN * 32 + lr) * 144 + lc * 16) + 18432;

    auto load_tile = [&](int t, int stage) {
        const uint32_t st = smBase + stage * GSTAGE;
        const int koff = t * 64;
        #pragma unroll
        for (int it = 0; it < 4; it++)
            cp_async16(st + dstOff[it], srcA[it] + koff);
        #pragma unroll
        for (int it = 0; it < 4; it++)
            cp_async16(st + 18432 + dstOff[it], srcB[it] + koff);
    };

    float acc[4][4][4] = {};

    load_tile(0, 0); cp_commit();
    load_tile(1, 1); cp_commit();

    #pragma unroll
    for (int t = 0; t < 8; t++) {
        cp_wait<1>();
        __syncthreads();
        if (t + 2 < 8) load_tile(t + 2, (t + 2) % 3);
        cp_commit();

        const uint32_t sa = smBase + (t % 3) * GSTAGE;
        #pragma unroll
        for (int ks = 0; ks < 4; ks++) {
            const int ko2 = ks * 32;
            unsigned af[4][4], bfm[2][4];
            #pragma unroll
            for (int ma = 0; ma < 4; ma++)
                ldm_x4(af[ma], sa + aoff + ma * 16 * 144 + ko2);
            #pragma unroll
            for (int p = 0; p < 2; p++)
                ldm_x4(bfm[p], sa + boff + p * 16 * 144 + ko2);
            #pragma unroll
            for (int ma = 0; ma < 4; ma++)
                #pragma unroll
                for (int nb = 0; nb < 4; nb++)
                    mma16816(acc[ma][nb], af[ma],
                             bfm[nb >> 1][nb & 1], bfm[nb >> 1][2 + (nb & 1)]);
        }
    }

    float2 bv[4];
    #pragma unroll
    for (int nb = 0; nb < 4; nb++)
        bv[nb] = *(const float2*)&bias[bn + warpN * 32 + nb * 8 + t2];

    #pragma unroll
    for (int ma = 0; ma < 4; ma++)
        #pragma unroll
        for (int h2 = 0; h2 < 2; h2++) {
            int m = bm + warpM * 64 + ma * 16 + h2 * 8 + g;
            #pragma unroll
            for (int nb = 0; nb < 4; nb++) {
                int n = bn + warpN * 32 + nb * 8 + t2;
                float2 s = *(const float2*)&shortcut[(size_t)m * CDIM + n];
                float2 o;
                o.x = acc[ma][nb][h2 * 2 + 0] + bv[nb].x + s.x;
                o.y = acc[ma][nb][h2 * 2 + 1] + bv[nb].y + s.y;
                *(float2*)&out[(size_t)m * CDIM + n] = o;
            }
        }
}

// ---------------------------------------------------------------------------
// Attention (R10 proven): block = (128 q-rows, h, bt), 8 warps, warp 16q x 64k.
// Per-16-key streaming softmax; 2 CTA/SM at 128 regs.
// ---------------------------------------------------------------------------
#define ASMEM 73728

__global__ __launch_bounds__(256, 2)
void attn_bf16()
{
    extern __shared__ bf16 dsm[];
    bf16* Qs = dsm;
    const uint32_t smQ = smem_u32(dsm);
    const uint32_t smK = smQ + 9216 * 2;
    const uint32_t smV = smK + 13824 * 2;

    const int tid  = threadIdx.x;
    const int lane = tid & 31;
    const int wid  = tid >> 5;
    const int g    = lane >> 2;
    const int t2   = (lane & 3) * 2;
    const int lr   = lane & 15;
    const int lc   = lane >> 4;
    const int qt   = blockIdx.x;
    const int h    = blockIdx.y;
    const int bt   = blockIdx.z;

    const bf16* Qg = g_qh + (((size_t)(bt * 8 + h)) * 256 + qt * 128) * 64;
    const bf16* Kg = g_kh + ((size_t)(bt * 8 + h)) * 512 * 64;
    const bf16* Vg = g_vh + ((size_t)(bt * 8 + h)) * 512 * 64;

    auto load_kv = [&](int t) {
        const int stage = t % 3;
        const uint32_t kb = smK + stage * 4608 * 2;
        const uint32_t vb = smV + stage * 4608 * 2;
        #pragma unroll
        for (int it = 0; it < 2; it++) {
            int c   = tid + it * 256;
            int row = c >> 3;
            int cc  = c & 7;
            cp_async16(kb + row * 144 + cc * 16, Kg + (size_t)(t * 64 + row) * 64 + cc * 8);
            cp_async16(vb + row * 144 + cc * 16, Vg + (size_t)(t * 64 + row) * 64 + cc * 8);
        }
    };

    load_kv(0); cp_commit();
    load_kv(1); cp_commit();

    #pragma unroll
    for (int it = 0; it < 4; it++) {
        int idx = tid + it * 256;
        int row = idx >> 3, c = (idx & 7) * 8;
        *(uint4*)&Qs[row * 72 + c] = *(const uint4*)&Qg[(size_t)row * 64 + c];
    }
    __syncthreads();

    unsigned qf[4][4];
    {
        const uint32_t qoff = smQ + (uint32_t)((wid * 16 + lr) * 144 + lc * 16);
        #pragma unroll
        for (int ka = 0; ka < 4; ka++)
            ldm_x4(qf[ka], qoff + ka * 32);
    }

    const uint32_t nvoff = (uint32_t)(lr * 144 + lc * 16);

    float oacc[8][4] = {};
    float lsum0 = 0.f, lsum1 = 0.f;
    const float sc = 0.125f * 1.4426950408889634f;

    #pragma unroll
    for (int t = 0; t < 8; t++) {
        cp_wait<1>();
        __syncthreads();
        if (t + 2 < 8) load_kv(t + 2);
        cp_commit();

        const uint32_t kb = smK + (t % 3) * 4608 * 2;
        const uint32_t vb = smV + (t % 3) * 4608 * 2;

        #pragma unroll
        for (int p = 0; p < 4; p++) {
            float s0[4] = {}, s1[4] = {};
            #pragma unroll
            for (int ka = 0; ka < 4; ka++) {
                unsigned kf[4];
                ldm_x4(kf, kb + nvoff + p * 16 * 144 + ka * 32);
                mma16816(s0, qf[ka], kf[0], kf[2]);
                mma16816(s1, qf[ka], kf[1], kf[3]);
            }
            #pragma unroll
            for (int i = 0; i < 4; i++) {
                float e0, e1;
                asm("ex2.approx.f32 %0, %1;" : "=f"(e0) : "f"(s0[i] * sc));
                asm("ex2.approx.f32 %0, %1;" : "=f"(e1) : "f"(s1[i] * sc));
                s0[i] = e0; s1[i] = e1;
            }
            lsum0 += s0[0] + s0[1] + s1[0] + s1[1];
            lsum1 += s0[2] + s0[3] + s1[2] + s1[3];

            unsigned pf[4];
            pf[0] = pk(s0[0], s0[1]);
            pf[1] = pk(s0[2], s0[3]);
            pf[2] = pk(s1[0], s1[1]);
            pf[3] = pk(s1[2], s1[3]);

            #pragma unroll
            for (int d = 0; d < 4; d++) {
                unsigned vf[4];
                ldm_x4_t(vf, vb + (p * 16 + lr) * 144 + lc * 16 + d * 32);
                mma16816(oacc[2 * d + 0], pf, vf[0], vf[1]);
                mma16816(oacc[2 * d + 1], pf, vf[2], vf[3]);
            }
        }
    }

    lsum0 += __shfl_xor_sync(0xffffffffu, lsum0, 1);
    lsum0 += __shfl_xor_sync(0xffffffffu, lsum0, 2);
    lsum1 += __shfl_xor_sync(0xffffffffu, lsum1, 1);
    lsum1 += __shfl_xor_sync(0xffffffffu, lsum1, 2);
    const float rl0 = 1.f / lsum0, rl1 = 1.f / lsum1;

    bf16* Og = g_xm + ((size_t)bt * 256 + qt * 128) * 512 + h * 64;
    const int r0 = wid * 16 + g;
    #pragma unroll
    for (int nb = 0; nb < 8; nb++) {
        int n = nb * 8 + t2;
        *(unsigned*)&Og[(size_t)r0 * 512 + n]       = pk(oacc[nb][0] * rl0, oacc[nb][1] * rl0);
        *(unsigned*)&Og[(size_t)(r0 + 8) * 512 + n] = pk(oacc[nb][2] * rl1, oacc[nb][3] * rl1);
    }
}

// ---------------------------------------------------------------------------
extern "C" void kernel_launch(void* const* d_in, const int* in_sizes, int n_in,
                              void* d_out, int out_size)
{
    const float* q   = (const float*)d_in[0];
    const float* kv  = (const float*)d_in[1];
    const float* Wq  = (const float*)d_in[2];
    const float* bq  = (const float*)d_in[3];
    const float* Wkv = (const float*)d_in[4];
    const float* bkv = (const float*)d_in[5];
    const float* Wm  = (const float*)d_in[6];
    const float* bm  = (const float*)d_in[7];
    float* out = (float*)d_out;

    cudaFuncSetAttribute(proj_gemm, cudaFuncAttributeMaxDynamicSharedMemorySize, PSMEM);
    cudaFuncSetAttribute(out_gemm,  cudaFuncAttributeMaxDynamicSharedMemorySize, GSMEM);
    cudaFuncSetAttribute(attn_bf16, cudaFuncAttributeMaxDynamicSharedMemorySize, ASMEM);

    convert_all<<<ALL8 / 256, 256>>>(q, kv, Wq, Wkv, Wm);

    // merged Q+KV projection: 256 + 1024 CTAs, 512 threads, 1 CTA/SM
    proj_gemm<<<1280, 512, PSMEM>>>(bq, bkv);
    // cosine attention
    attn_bf16<<<dim3(2, 8, 64), 256, ASMEM>>>();
    // output projection + bias + residual
    out_gemm<<<dim3(4, 128), 256, GSMEM>>>(bm, q, out);
}

// round 12
// speedup vs baseline: 1.0816x; 1.0816x over previous
#include <cuda_runtime.h>
#include <cuda_bf16.h>
#include <math.h>
#include <stdint.h>

#define BT_N 64
#define LQ   256
#define LK   512
#define CDIM 512
#define NH   8
#define HD   64

typedef __nv_bfloat16 bf16;

// ---- device scratch ----
__device__ uint8_t g_qf8 [(size_t)16384 * 512];
__device__ uint8_t g_kvf8[(size_t)32768 * 512];
__device__ uint8_t g_wqf8 [512 * 512];
__device__ uint8_t g_wkvf8[1024 * 512];
__device__ bf16    g_wm  [512 * 512];
__device__ bf16    g_qh  [(size_t)BT_N * NH * LQ * HD];
__device__ bf16    g_kh  [(size_t)BT_N * NH * LK * HD];
__device__ bf16    g_vh  [(size_t)BT_N * NH * LK * HD];
__device__ bf16    g_xm  [(size_t)BT_N * LQ * CDIM];

// ---------------------------------------------------------------------------
__device__ __forceinline__ unsigned pk(float lo, float hi) {
    unsigned r;
    asm("cvt.rn.bf16x2.f32 %0, %1, %2;" : "=r"(r) : "f"(hi), "f"(lo));
    return r;
}
__device__ __forceinline__ unsigned short pk8(float lo, float hi) {
    unsigned short r;
    asm("cvt.rn.satfinite.e4m3x2.f32 %0, %1, %2;" : "=h"(r) : "f"(hi), "f"(lo));
    return r;
}
__device__ __forceinline__ uint32_t smem_u32(const void* p) {
    uint32_t a;
    asm("{ .reg .u64 t; cvta.to.shared.u64 t, %1; cvt.u32.u64 %0, t; }" : "=r"(a) : "l"(p));
    return a;
}
__device__ __forceinline__ void cp_async16(uint32_t dst, const void* src) {
    asm volatile("cp.async.cg.shared.global [%0], [%1], 16;" :: "r"(dst), "l"(src));
}
__device__ __forceinline__ void cp_commit() { asm volatile("cp.async.commit_group;" ::: "memory"); }
template<int N> __device__ __forceinline__ void cp_wait() { asm volatile("cp.async.wait_group %0;" :: "n"(N) : "memory"); }

__device__ __forceinline__ void ldm_x4(unsigned* r, uint32_t addr) {
    asm volatile("ldmatrix.sync.aligned.m8n8.x4.shared.b16 {%0,%1,%2,%3}, [%4];"
                 : "=r"(r[0]), "=r"(r[1]), "=r"(r[2]), "=r"(r[3]) : "r"(addr));
}
__device__ __forceinline__ void ldm_x4_t(unsigned* r, uint32_t addr) {
    asm volatile("ldmatrix.sync.aligned.m8n8.x4.trans.shared.b16 {%0,%1,%2,%3}, [%4];"
                 : "=r"(r[0]), "=r"(r[1]), "=r"(r[2]), "=r"(r[3]) : "r"(addr));
}

__device__ __forceinline__ void mma16816(float* d, const unsigned* a, unsigned b0, unsigned b1) {
    asm volatile(
        "mma.sync.aligned.m16n8k16.row.col.f32.bf16.bf16.f32 "
        "{%0,%1,%2,%3},{%4,%5,%6,%7},{%8,%9},{%0,%1,%2,%3};"
        : "+f"(d[0]), "+f"(d[1]), "+f"(d[2]), "+f"(d[3])
        : "r"(a[0]), "r"(a[1]), "r"(a[2]), "r"(a[3]), "r"(b0), "r"(b1));
}
__device__ __forceinline__ void mma_f8(float* d, const unsigned* a, unsigned b0, unsigned b1) {
    asm volatile(
        "mma.sync.aligned.m16n8k32.row.col.f32.e4m3.e4m3.f32 "
        "{%0,%1,%2,%3},{%4,%5,%6,%7},{%8,%9},{%0,%1,%2,%3};"
        : "+f"(d[0]), "+f"(d[1]), "+f"(d[2]), "+f"(d[3])
        : "r"(a[0]), "r"(a[1]), "r"(a[2]), "r"(a[3]), "r"(b0), "r"(b1));
}

// ---------------------------------------------------------------------------
// fp32 -> fp8/bf16 conversion, single kernel (unit = 8 elements)
// weights for fp8 GEMMs are pre-scaled x32 (epilogue multiplies by 1/32)
// ---------------------------------------------------------------------------
#define Q8   (16384 * 512 / 8)
#define KV8  (32768 * 512 / 8)
#define WQ8  (512 * 512 / 8)
#define WKV8 (1024 * 512 / 8)
#define WM8  (512 * 512 / 8)
#define ALL8 (Q8 + KV8 + WQ8 + WKV8 + WM8)

__device__ __forceinline__ void conv8_f8(const float* src, uint8_t* dst, int i, float s) {
    float4 a = ((const float4*)src)[2 * i];
    float4 b = ((const float4*)src)[2 * i + 1];
    unsigned short p0 = pk8(a.x * s, a.y * s), p1 = pk8(a.z * s, a.w * s);
    unsigned short p2 = pk8(b.x * s, b.y * s), p3 = pk8(b.z * s, b.w * s);
    ((uint2*)dst)[i] = make_uint2((unsigned)p0 | ((unsigned)p1 << 16),
                                  (unsigned)p2 | ((unsigned)p3 << 16));
}
__device__ __forceinline__ void conv8_bf(const float* src, bf16* dst, int i) {
    const float4 a = ((const float4*)src)[2 * i];
    const float4 b = ((const float4*)src)[2 * i + 1];
    ((uint4*)dst)[i] = make_uint4(pk(a.x, a.y), pk(a.z, a.w), pk(b.x, b.y), pk(b.z, b.w));
}

__global__ __launch_bounds__(256)
void convert_all(const float* __restrict__ q, const float* __restrict__ kv,
                 const float* __restrict__ wq, const float* __restrict__ wkv,
                 const float* __restrict__ wm) {
    int i = blockIdx.x * blockDim.x + threadIdx.x;
    if (i < Q8)                          conv8_f8(q,   g_qf8,   i, 1.0f);
    else if (i < Q8 + KV8)               conv8_f8(kv,  g_kvf8,  i - Q8, 1.0f);
    else if (i < Q8 + KV8 + WQ8)         conv8_f8(wq,  g_wqf8,  i - Q8 - KV8, 32.0f);
    else if (i < Q8 + KV8 + WQ8 + WKV8)  conv8_f8(wkv, g_wkvf8, i - Q8 - KV8 - WQ8, 32.0f);
    else                                 conv8_bf(wm,  g_wm,    i - Q8 - KV8 - WQ8 - WKV8);
}

// ---------------------------------------------------------------------------
// FP8 projection GEMM (NT): CTA 128x128, BK=128 bytes, 3-stage cp.async.
// 8 warps 2M x 4N, warp tile 64x32, mma m16n8k32 e4m3. Row stride 144 B.
// Stage = 36864 B; 3 stages -> 2 CTA/SM (16 warps/SM).
// MODE 0: q proj -> g_qh; MODE 1: kv proj -> g_kh / g_vh. L2-norm epilogue.
// ---------------------------------------------------------------------------
#define GSTAGE 36864
#define GSMEM  (3 * GSTAGE)

template<int MODE>
__global__ __launch_bounds__(256, 2)
void proj_f8(const float* __restrict__ bias)
{
    extern __shared__ uint8_t dsm8[];
    __shared__ float sred[512];
    const uint32_t smBase = smem_u32(dsm8);

    const int tid   = threadIdx.x;
    const int lane  = tid & 31;
    const int wid   = tid >> 5;
    const int warpM = wid >> 2;
    const int warpN = wid & 3;
    const int g     = lane >> 2;
    const int t2    = (lane & 3) * 2;
    const int lr    = lane & 15;
    const int lc    = lane >> 4;
    const int bm    = blockIdx.y * 128;
    const int bn    = blockIdx.x * 128;

    const uint8_t* A = (MODE == 0) ? g_qf8  : g_kvf8;
    const uint8_t* W = (MODE == 0) ? g_wqf8 : g_wkvf8;

    // loader: A 128 rows x 128 B (8 chunks/row), B same; 4+4 chunks per thread
    const int lrow = tid >> 3;
    const int lcc  = tid & 7;
    const uint8_t* srcA[4];
    const uint8_t* srcB[4];
    uint32_t dstOff[4];
    #pragma unroll
    for (int it = 0; it < 4; it++) {
        int row = lrow + it * 32;
        srcA[it] = A + (size_t)(bm + row) * CDIM + lcc * 16;
        srcB[it] = W + (size_t)(bn + row) * CDIM + lcc * 16;
        dstOff[it] = (uint32_t)(row * 144 + lcc * 16);
    }

    const uint32_t aoff = (uint32_t)((warpM * 64 + lr) * 144 + lc * 16);
    const uint32_t boff = (uint32_t)((warpN * 32 + lr) * 144 + lc * 16) + 18432;

    auto load_tile = [&](int t, int stage) {
        const uint32_t st = smBase + stage * GSTAGE;
        const int koff = t * 128;
        #pragma unroll
        for (int it = 0; it < 4; it++)
            cp_async16(st + dstOff[it], srcA[it] + koff);
        #pragma unroll
        for (int it = 0; it < 4; it++)
            cp_async16(st + 18432 + dstOff[it], srcB[it] + koff);
    };

    float acc[4][4][4] = {};

    load_tile(0, 0); cp_commit();
    load_tile(1, 1); cp_commit();

    #pragma unroll
    for (int t = 0; t < 4; t++) {
        cp_wait<1>();
        __syncthreads();
        if (t + 2 < 4) load_tile(t + 2, (t + 2) % 3);
        cp_commit();

        const uint32_t sa = smBase + (t % 3) * GSTAGE;
        #pragma unroll
        for (int ks = 0; ks < 4; ks++) {
            const int ko2 = ks * 32;          // 32 fp8 = 32 bytes per k-step
            unsigned af[4][4], bfm[2][4];
            #pragma unroll
            for (int ma = 0; ma < 4; ma++)
                ldm_x4(af[ma], sa + aoff + ma * 16 * 144 + ko2);
            #pragma unroll
            for (int p = 0; p < 2; p++)
                ldm_x4(bfm[p], sa + boff + p * 16 * 144 + ko2);
            #pragma unroll
            for (int ma = 0; ma < 4; ma++)
                #pragma unroll
                for (int nb = 0; nb < 4; nb++)
                    mma_f8(acc[ma][nb], af[ma],
                           bfm[nb >> 1][nb & 1], bfm[nb >> 1][2 + (nb & 1)]);
        }
    }

    // undo weight prescale, add bias
    float2 bv[4];
    #pragma unroll
    for (int nb = 0; nb < 4; nb++)
        bv[nb] = *(const float2*)&bias[bn + warpN * 32 + nb * 8 + t2];
    #pragma unroll
    for (int ma = 0; ma < 4; ma++)
        #pragma unroll
        for (int nb = 0; nb < 4; nb++) {
            acc[ma][nb][0] = acc[ma][nb][0] * 0.03125f + bv[nb].x;
            acc[ma][nb][1] = acc[ma][nb][1] * 0.03125f + bv[nb].y;
            acc[ma][nb][2] = acc[ma][nb][2] * 0.03125f + bv[nb].x;
            acc[ma][nb][3] = acc[ma][nb][3] * 0.03125f + bv[nb].y;
        }

    // L2 norm over 64-wide head chunks (pair of adjacent warps shares a head)
    float ssq[4][2];
    #pragma unroll
    for (int ma = 0; ma < 4; ma++)
        #pragma unroll
        for (int h2 = 0; h2 < 2; h2++) {
            float s = 0.f;
            #pragma unroll
            for (int nb = 0; nb < 4; nb++) {
                float x = acc[ma][nb][h2 * 2], y = acc[ma][nb][h2 * 2 + 1];
                s += x * x + y * y;
            }
            s += __shfl_xor_sync(0xffffffffu, s, 1);
            s += __shfl_xor_sync(0xffffffffu, s, 2);
            ssq[ma][h2] = s;
        }
    __syncthreads();
    if ((lane & 3) == 0) {
        #pragma unroll
        for (int ma = 0; ma < 4; ma++)
            #pragma unroll
            for (int h2 = 0; h2 < 2; h2++)
                sred[wid * 64 + ma * 16 + h2 * 8 + g] = ssq[ma][h2];
    }
    __syncthreads();
    #pragma unroll
    for (int ma = 0; ma < 4; ma++)
        #pragma unroll
        for (int h2 = 0; h2 < 2; h2++) {
            int r = ma * 16 + h2 * 8 + g;
            float tot = sred[(wid & ~1) * 64 + r] + sred[((wid & ~1) + 1) * 64 + r];
            float rn = 1.f / fmaxf(sqrtf(tot), 1e-12f);
            int m = bm + warpM * 64 + r;
            #pragma unroll
            for (int nb = 0; nb < 4; nb++) {
                int n = bn + warpN * 32 + nb * 8 + t2;
                float v0 = acc[ma][nb][h2 * 2] * rn;
                float v1 = acc[ma][nb][h2 * 2 + 1] * rn;
                if (MODE == 0) {
                    int bt = m >> 8, lq = m & 255;
                    int h = n >> 6, d = n & 63;
                    *(unsigned*)&g_qh[(((size_t)(bt * 8 + h)) * 256 + lq) * 64 + d] = pk(v0, v1);
                } else {
                    int bt = m >> 9, lk = m & 511;
                    int h = (n >> 6) & 7, d = n & 63;
                    bf16* base = (n < 512) ? g_kh : g_vh;
                    *(unsigned*)&base[(((size_t)(bt * 8 + h)) * 512 + lk) * 64 + d] = pk(v0, v1);
                }
            }
        }
}

// ---------------------------------------------------------------------------
// Output GEMM (bf16, R7/R10 proven): CTA 128x128, BK=64, 8 warps 2Mx4N.
// ---------------------------------------------------------------------------
__global__ __launch_bounds__(256, 2)
void out_gemm(const float* __restrict__ bias,
              const float* __restrict__ shortcut,
              float* __restrict__ out)
{
    extern __shared__ uint8_t dsm8[];
    bf16* dsm = (bf16*)dsm8;
    const uint32_t smBase = smem_u32(dsm);

    const int tid   = threadIdx.x;
    const int lane  = tid & 31;
    const int wid   = tid >> 5;
    const int warpM = wid >> 2;
    const int warpN = wid & 3;
    const int g     = lane >> 2;
    const int t2    = (lane & 3) * 2;
    const int lr    = lane & 15;
    const int lc    = lane >> 4;
    const int bm    = blockIdx.y * 128;
    const int bn    = blockIdx.x * 128;

    const bf16* A = g_xm;
    const bf16* W = g_wm;

    const int lrow = tid >> 3;
    const int lcc  = tid & 7;
    const bf16* srcA[4];
    const bf16* srcB[4];
    uint32_t dstOff[4];
    #pragma unroll
    for (int it = 0; it < 4; it++) {
        int row = lrow + it * 32;
        srcA[it] = A + (size_t)(bm + row) * CDIM + lcc * 8;
        srcB[it] = W + (size_t)(bn + row) * CDIM + lcc * 8;
        dstOff[it] = (uint32_t)(row * 144 + lcc * 16);
    }

    const uint32_t aoff = (uint32_t)((warpM * 64 + lr) * 144 + lc * 16);
    const uint32_t boff = (uint32_t)((warpN * 32 + lr) * 144 + lc * 16) + 18432;

    auto load_tile = [&](int t, int stage) {
        const uint32_t st = smBase + stage * GSTAGE;
        const int koff = t * 64;
        #pragma unroll
        for (int it = 0; it < 4; it++)
            cp_async16(st + dstOff[it], srcA[it] + koff);
        #pragma unroll
        for (int it = 0; it < 4; it++)
            cp_async16(st + 18432 + dstOff[it], srcB[it] + koff);
    };

    float acc[4][4][4] = {};

    load_tile(0, 0); cp_commit();
    load_tile(1, 1); cp_commit();

    #pragma unroll
    for (int t = 0; t < 8; t++) {
        cp_wait<1>();
        __syncthreads();
        if (t + 2 < 8) load_tile(t + 2, (t + 2) % 3);
        cp_commit();

        const uint32_t sa = smBase + (t % 3) * GSTAGE;
        #pragma unroll
        for (int ks = 0; ks < 4; ks++) {
            const int ko2 = ks * 32;
            unsigned af[4][4], bfm[2][4];
            #pragma unroll
            for (int ma = 0; ma < 4; ma++)
                ldm_x4(af[ma], sa + aoff + ma * 16 * 144 + ko2);
            #pragma unroll
            for (int p = 0; p < 2; p++)
                ldm_x4(bfm[p], sa + boff + p * 16 * 144 + ko2);
            #pragma unroll
            for (int ma = 0; ma < 4; ma++)
                #pragma unroll
                for (int nb = 0; nb < 4; nb++)
                    mma16816(acc[ma][nb], af[ma],
                             bfm[nb >> 1][nb & 1], bfm[nb >> 1][2 + (nb & 1)]);
        }
    }

    float2 bv[4];
    #pragma unroll
    for (int nb = 0; nb < 4; nb++)
        bv[nb] = *(const float2*)&bias[bn + warpN * 32 + nb * 8 + t2];

    #pragma unroll
    for (int ma = 0; ma < 4; ma++)
        #pragma unroll
        for (int h2 = 0; h2 < 2; h2++) {
            int m = bm + warpM * 64 + ma * 16 + h2 * 8 + g;
            #pragma unroll
            for (int nb = 0; nb < 4; nb++) {
                int n = bn + warpN * 32 + nb * 8 + t2;
                float2 s = *(const float2*)&shortcut[(size_t)m * CDIM + n];
                float2 o;
                o.x = acc[ma][nb][h2 * 2 + 0] + bv[nb].x + s.x;
                o.y = acc[ma][nb][h2 * 2 + 1] + bv[nb].y + s.y;
                *(float2*)&out[(size_t)m * CDIM + n] = o;
            }
        }
}

// ---------------------------------------------------------------------------
// Attention (R10 proven): block = (128 q-rows, h, bt), 8 warps, warp 16q x 64k.
// Per-16-key streaming softmax; 2 CTA/SM at 128 regs.
// ---------------------------------------------------------------------------
#define ASMEM 73728

__global__ __launch_bounds__(256, 2)
void attn_bf16()
{
    extern __shared__ uint8_t dsm8[];
    bf16* Qs = (bf16*)dsm8;
    const uint32_t smQ = smem_u32(Qs);
    const uint32_t smK = smQ + 9216 * 2;
    const uint32_t smV = smK + 13824 * 2;

    const int tid  = threadIdx.x;
    const int lane = tid & 31;
    const int wid  = tid >> 5;
    const int g    = lane >> 2;
    const int t2   = (lane & 3) * 2;
    const int lr   = lane & 15;
    const int lc   = lane >> 4;
    const int qt   = blockIdx.x;
    const int h    = blockIdx.y;
    const int bt   = blockIdx.z;

    const bf16* Qg = g_qh + (((size_t)(bt * 8 + h)) * 256 + qt * 128) * 64;
    const bf16* Kg = g_kh + ((size_t)(bt * 8 + h)) * 512 * 64;
    const bf16* Vg = g_vh + ((size_t)(bt * 8 + h)) * 512 * 64;

    auto load_kv = [&](int t) {
        const int stage = t % 3;
        const uint32_t kb = smK + stage * 4608 * 2;
        const uint32_t vb = smV + stage * 4608 * 2;
        #pragma unroll
        for (int it = 0; it < 2; it++) {
            int c   = tid + it * 256;
            int row = c >> 3;
            int cc  = c & 7;
            cp_async16(kb + row * 144 + cc * 16, Kg + (size_t)(t * 64 + row) * 64 + cc * 8);
            cp_async16(vb + row * 144 + cc * 16, Vg + (size_t)(t * 64 + row) * 64 + cc * 8);
        }
    };

    load_kv(0); cp_commit();
    load_kv(1); cp_commit();

    #pragma unroll
    for (int it = 0; it < 4; it++) {
        int idx = tid + it * 256;
        int row = idx >> 3, c = (idx & 7) * 8;
        *(uint4*)&Qs[row * 72 + c] = *(const uint4*)&Qg[(size_t)row * 64 + c];
    }
    __syncthreads();

    unsigned qf[4][4];
    {
        const uint32_t qoff = smQ + (uint32_t)((wid * 16 + lr) * 144 + lc * 16);
        #pragma unroll
        for (int ka = 0; ka < 4; ka++)
            ldm_x4(qf[ka], qoff + ka * 32);
    }

    const uint32_t nvoff = (uint32_t)(lr * 144 + lc * 16);

    float oacc[8][4] = {};
    float lsum0 = 0.f, lsum1 = 0.f;
    const float sc = 0.125f * 1.4426950408889634f;

    #pragma unroll
    for (int t = 0; t < 8; t++) {
        cp_wait<1>();
        __syncthreads();
        if (t + 2 < 8) load_kv(t + 2);
        cp_commit();

        const uint32_t kb = smK + (t % 3) * 4608 * 2;
        const uint32_t vb = smV + (t % 3) * 4608 * 2;

        #pragma unroll
        for (int p = 0; p < 4; p++) {
            float s0[4] = {}, s1[4] = {};
            #pragma unroll
            for (int ka = 0; ka < 4; ka++) {
                unsigned kf[4];
                ldm_x4(kf, kb + nvoff + p * 16 * 144 + ka * 32);
                mma16816(s0, qf[ka], kf[0], kf[2]);
                mma16816(s1, qf[ka], kf[1], kf[3]);
            }
            #pragma unroll
            for (int i = 0; i < 4; i++) {
                float e0, e1;
                asm("ex2.approx.f32 %0, %1;" : "=f"(e0) : "f"(s0[i] * sc));
                asm("ex2.approx.f32 %0, %1;" : "=f"(e1) : "f"(s1[i] * sc));
                s0[i] = e0; s1[i] = e1;
            }
            lsum0 += s0[0] + s0[1] + s1[0] + s1[1];
            lsum1 += s0[2] + s0[3] + s1[2] + s1[3];

            unsigned pf[4];
            pf[0] = pk(s0[0], s0[1]);
            pf[1] = pk(s0[2], s0[3]);
            pf[2] = pk(s1[0], s1[1]);
            pf[3] = pk(s1[2], s1[3]);

            #pragma unroll
            for (int d = 0; d < 4; d++) {
                unsigned vf[4];
                ldm_x4_t(vf, vb + (p * 16 + lr) * 144 + lc * 16 + d * 32);
                mma16816(oacc[2 * d + 0], pf, vf[0], vf[1]);
                mma16816(oacc[2 * d + 1], pf, vf[2], vf[3]);
            }
        }
    }

    lsum0 += __shfl_xor_sync(0xffffffffu, lsum0, 1);
    lsum0 += __shfl_xor_sync(0xffffffffu, lsum0, 2);
    lsum1 += __shfl_xor_sync(0xffffffffu, lsum1, 1);
    lsum1 += __shfl_xor_sync(0xffffffffu, lsum1, 2);
    const float rl0 = 1.f / lsum0, rl1 = 1.f / lsum1;

    bf16* Og = g_xm + ((size_t)bt * 256 + qt * 128) * 512 + h * 64;
    const int r0 = wid * 16 + g;
    #pragma unroll
    for (int nb = 0; nb < 8; nb++) {
        int n = nb * 8 + t2;
        *(unsigned*)&Og[(size_t)r0 * 512 + n]       = pk(oacc[nb][0] * rl0, oacc[nb][1] * rl0);
        *(unsigned*)&Og[(size_t)(r0 + 8) * 512 + n] = pk(oacc[nb][2] * rl1, oacc[nb][3] * rl1);
    }
}

// ---------------------------------------------------------------------------
extern "C" void kernel_launch(void* const* d_in, const int* in_sizes, int n_in,
                              void* d_out, int out_size)
{
    const float* q   = (const float*)d_in[0];
    const float* kv  = (const float*)d_in[1];
    const float* Wq  = (const float*)d_in[2];
    const float* bq  = (const float*)d_in[3];
    const float* Wkv = (const float*)d_in[4];
    const float* bkv = (const float*)d_in[5];
    const float* Wm  = (const float*)d_in[6];
    const float* bm  = (const float*)d_in[7];
    float* out = (float*)d_out;

    cudaFuncSetAttribute(proj_f8<0>, cudaFuncAttributeMaxDynamicSharedMemorySize, GSMEM);
    cudaFuncSetAttribute(proj_f8<1>, cudaFuncAttributeMaxDynamicSharedMemorySize, GSMEM);
    cudaFuncSetAttribute(out_gemm,   cudaFuncAttributeMaxDynamicSharedMemorySize, GSMEM);
    cudaFuncSetAttribute(attn_bf16,  cudaFuncAttributeMaxDynamicSharedMemorySize, ASMEM);

    convert_all<<<ALL8 / 256, 256>>>(q, kv, Wq, Wkv, Wm);

    proj_f8<0><<<dim3(4, 128), 256, GSMEM>>>(bq);    // 16384 x 512
    proj_f8<1><<<dim3(8, 256), 256, GSMEM>>>(bkv);   // 32768 x 1024
    attn_bf16<<<dim3(2, 8, 64), 256, ASMEM>>>();
    out_gemm<<<dim3(4, 128), 256, GSMEM>>>(bm, q, out);
}

// round 13
// speedup vs baseline: 1.0988x; 1.0158x over previous
#include <cuda_runtime.h>
#include <cuda_bf16.h>
#include <math.h>
#include <stdint.h>

#define BT_N 64
#define LQ   256
#define LK   512
#define CDIM 512
#define NH   8
#define HD   64

typedef __nv_bfloat16 bf16;

// ---- device scratch ----
__device__ uint8_t g_qf8 [(size_t)16384 * 512];
__device__ uint8_t g_kvf8[(size_t)32768 * 512];
__device__ uint8_t g_wqf8 [512 * 512];
__device__ uint8_t g_wkvf8[1024 * 512];
__device__ bf16    g_wm  [512 * 512];
__device__ uint8_t g_qh8 [(size_t)BT_N * NH * LQ * HD];   // fp8, x4 prescale
__device__ uint8_t g_kh8 [(size_t)BT_N * NH * LK * HD];   // fp8, x4 prescale
__device__ bf16    g_vh  [(size_t)BT_N * NH * LK * HD];   // bf16 row-major
__device__ bf16    g_xm  [(size_t)BT_N * LQ * CDIM];

// ---------------------------------------------------------------------------
__device__ __forceinline__ unsigned pk(float lo, float hi) {
    unsigned r;
    asm("cvt.rn.bf16x2.f32 %0, %1, %2;" : "=r"(r) : "f"(hi), "f"(lo));
    return r;
}
__device__ __forceinline__ unsigned short pk8(float lo, float hi) {
    unsigned short r;
    asm("cvt.rn.satfinite.e4m3x2.f32 %0, %1, %2;" : "=h"(r) : "f"(hi), "f"(lo));
    return r;
}
__device__ __forceinline__ uint32_t smem_u32(const void* p) {
    uint32_t a;
    asm("{ .reg .u64 t; cvta.to.shared.u64 t, %1; cvt.u32.u64 %0, t; }" : "=r"(a) : "l"(p));
    return a;
}
__device__ __forceinline__ void cp_async16(uint32_t dst, const void* src) {
    asm volatile("cp.async.cg.shared.global [%0], [%1], 16;" :: "r"(dst), "l"(src));
}
__device__ __forceinline__ void cp_commit() { asm volatile("cp.async.commit_group;" ::: "memory"); }
template<int N> __device__ __forceinline__ void cp_wait() { asm volatile("cp.async.wait_group %0;" :: "n"(N) : "memory"); }

__device__ __forceinline__ void ldm_x4(unsigned* r, uint32_t addr) {
    asm volatile("ldmatrix.sync.aligned.m8n8.x4.shared.b16 {%0,%1,%2,%3}, [%4];"
                 : "=r"(r[0]), "=r"(r[1]), "=r"(r[2]), "=r"(r[3]) : "r"(addr));
}
__device__ __forceinline__ void ldm_x4_t(unsigned* r, uint32_t addr) {
    asm volatile("ldmatrix.sync.aligned.m8n8.x4.trans.shared.b16 {%0,%1,%2,%3}, [%4];"
                 : "=r"(r[0]), "=r"(r[1]), "=r"(r[2]), "=r"(r[3]) : "r"(addr));
}

__device__ __forceinline__ void mma16816(float* d, const unsigned* a, unsigned b0, unsigned b1) {
    asm volatile(
        "mma.sync.aligned.m16n8k16.row.col.f32.bf16.bf16.f32 "
        "{%0,%1,%2,%3},{%4,%5,%6,%7},{%8,%9},{%0,%1,%2,%3};"
        : "+f"(d[0]), "+f"(d[1]), "+f"(d[2]), "+f"(d[3])
        : "r"(a[0]), "r"(a[1]), "r"(a[2]), "r"(a[3]), "r"(b0), "r"(b1));
}
__device__ __forceinline__ void mma_f8(float* d, const unsigned* a, unsigned b0, unsigned b1) {
    asm volatile(
        "mma.sync.aligned.m16n8k32.row.col.f32.e4m3.e4m3.f32 "
        "{%0,%1,%2,%3},{%4,%5,%6,%7},{%8,%9},{%0,%1,%2,%3};"
        : "+f"(d[0]), "+f"(d[1]), "+f"(d[2]), "+f"(d[3])
        : "r"(a[0]), "r"(a[1]), "r"(a[2]), "r"(a[3]), "r"(b0), "r"(b1));
}

// ---------------------------------------------------------------------------
// fp32 -> fp8/bf16 conversion (unit = 8 elements); fp8 weights prescaled x32
// ---------------------------------------------------------------------------
#define Q8   (16384 * 512 / 8)
#define KV8  (32768 * 512 / 8)
#define WQ8  (512 * 512 / 8)
#define WKV8 (1024 * 512 / 8)
#define WM8  (512 * 512 / 8)
#define ALL8 (Q8 + KV8 + WQ8 + WKV8 + WM8)

__device__ __forceinline__ void conv8_f8(const float* src, uint8_t* dst, int i, float s) {
    float4 a = ((const float4*)src)[2 * i];
    float4 b = ((const float4*)src)[2 * i + 1];
    unsigned short p0 = pk8(a.x * s, a.y * s), p1 = pk8(a.z * s, a.w * s);
    unsigned short p2 = pk8(b.x * s, b.y * s), p3 = pk8(b.z * s, b.w * s);
    ((uint2*)dst)[i] = make_uint2((unsigned)p0 | ((unsigned)p1 << 16),
                                  (unsigned)p2 | ((unsigned)p3 << 16));
}
__device__ __forceinline__ void conv8_bf(const float* src, bf16* dst, int i) {
    const float4 a = ((const float4*)src)[2 * i];
    const float4 b = ((const float4*)src)[2 * i + 1];
    ((uint4*)dst)[i] = make_uint4(pk(a.x, a.y), pk(a.z, a.w), pk(b.x, b.y), pk(b.z, b.w));
}

__global__ __launch_bounds__(256)
void convert_all(const float* __restrict__ q, const float* __restrict__ kv,
                 const float* __restrict__ wq, const float* __restrict__ wkv,
                 const float* __restrict__ wm) {
    int i = blockIdx.x * blockDim.x + threadIdx.x;
    if (i < Q8)                          conv8_f8(q,   g_qf8,   i, 1.0f);
    else if (i < Q8 + KV8)               conv8_f8(kv,  g_kvf8,  i - Q8, 1.0f);
    else if (i < Q8 + KV8 + WQ8)         conv8_f8(wq,  g_wqf8,  i - Q8 - KV8, 32.0f);
    else if (i < Q8 + KV8 + WQ8 + WKV8)  conv8_f8(wkv, g_wkvf8, i - Q8 - KV8 - WQ8, 32.0f);
    else                                 conv8_bf(wm,  g_wm,    i - Q8 - KV8 - WQ8 - WKV8);
}

// ---------------------------------------------------------------------------
// Merged FP8 projection GEMM: blocks [0,512) = Q proj, [512,2560) = KV proj.
// CTA 128x128, BK=128B, 3-stage cp.async, 8 warps 2Mx4N, 144B row stride.
// Epilogue: x1/32 + bias, L2-norm; q/k stored fp8 (x4), v stored bf16.
// ---------------------------------------------------------------------------
#define GSTAGE 36864
#define GSMEM  (3 * GSTAGE)

__global__ __launch_bounds__(256, 2)
void proj_f8(const float* __restrict__ bq, const float* __restrict__ bkv)
{
    extern __shared__ uint8_t dsm8[];
    __shared__ float sred[512];
    const uint32_t smBase = smem_u32(dsm8);

    const int tid   = threadIdx.x;
    const int lane  = tid & 31;
    const int wid   = tid >> 5;
    const int warpM = wid >> 2;
    const int warpN = wid & 3;
    const int g     = lane >> 2;
    const int t2    = (lane & 3) * 2;
    const int lr    = lane & 15;
    const int lc    = lane >> 4;

    const bool isQ = blockIdx.x < 512;
    int bm, bn;
    const uint8_t *A, *W;
    const float* bias;
    if (isQ) {
        int b = blockIdx.x;
        bn = (b & 3) * 128; bm = (b >> 2) * 128;
        A = g_qf8;  W = g_wqf8;  bias = bq;
    } else {
        int b = blockIdx.x - 512;
        bn = (b & 7) * 128; bm = (b >> 3) * 128;
        A = g_kvf8; W = g_wkvf8; bias = bkv;
    }

    const int lrow = tid >> 3;
    const int lcc  = tid & 7;
    const uint8_t* srcA[4];
    const uint8_t* srcB[4];
    uint32_t dstOff[4];
    #pragma unroll
    for (int it = 0; it < 4; it++) {
        int row = lrow + it * 32;
        srcA[it] = A + (size_t)(bm + row) * CDIM + lcc * 16;
        srcB[it] = W + (size_t)(bn + row) * CDIM + lcc * 16;
        dstOff[it] = (uint32_t)(row * 144 + lcc * 16);
    }

    const uint32_t aoff = (uint32_t)((warpM * 64 + lr) * 144 + lc * 16);
    const uint32_t boff = (uint32_t)((warpN * 32 + lr) * 144 + lc * 16) + 18432;

    auto load_tile = [&](int t, int stage) {
        const uint32_t st = smBase + stage * GSTAGE;
        const int koff = t * 128;
        #pragma unroll
        for (int it = 0; it < 4; it++)
            cp_async16(st + dstOff[it], srcA[it] + koff);
        #pragma unroll
        for (int it = 0; it < 4; it++)
            cp_async16(st + 18432 + dstOff[it], srcB[it] + koff);
    };

    float acc[4][4][4] = {};

    load_tile(0, 0); cp_commit();
    load_tile(1, 1); cp_commit();

    #pragma unroll
    for (int t = 0; t < 4; t++) {
        cp_wait<1>();
        __syncthreads();
        if (t + 2 < 4) load_tile(t + 2, (t + 2) % 3);
        cp_commit();

        const uint32_t sa = smBase + (t % 3) * GSTAGE;
        #pragma unroll
        for (int ks = 0; ks < 4; ks++) {
            const int ko2 = ks * 32;
            unsigned af[4][4], bfm[2][4];
            #pragma unroll
            for (int ma = 0; ma < 4; ma++)
                ldm_x4(af[ma], sa + aoff + ma * 16 * 144 + ko2);
            #pragma unroll
            for (int p = 0; p < 2; p++)
                ldm_x4(bfm[p], sa + boff + p * 16 * 144 + ko2);
            #pragma unroll
            for (int ma = 0; ma < 4; ma++)
                #pragma unroll
                for (int nb = 0; nb < 4; nb++)
                    mma_f8(acc[ma][nb], af[ma],
                           bfm[nb >> 1][nb & 1], bfm[nb >> 1][2 + (nb & 1)]);
        }
    }

    // undo weight prescale (x1/32), add bias
    float2 bv[4];
    #pragma unroll
    for (int nb = 0; nb < 4; nb++)
        bv[nb] = *(const float2*)&bias[bn + warpN * 32 + nb * 8 + t2];
    #pragma unroll
    for (int ma = 0; ma < 4; ma++)
        #pragma unroll
        for (int nb = 0; nb < 4; nb++) {
            acc[ma][nb][0] = acc[ma][nb][0] * 0.03125f + bv[nb].x;
            acc[ma][nb][1] = acc[ma][nb][1] * 0.03125f + bv[nb].y;
            acc[ma][nb][2] = acc[ma][nb][2] * 0.03125f + bv[nb].x;
            acc[ma][nb][3] = acc[ma][nb][3] * 0.03125f + bv[nb].y;
        }

    // L2 norm over 64-wide head chunks
    float ssq[4][2];
    #pragma unroll
    for (int ma = 0; ma < 4; ma++)
        #pragma unroll
        for (int h2 = 0; h2 < 2; h2++) {
            float s = 0.f;
            #pragma unroll
            for (int nb = 0; nb < 4; nb++) {
                float x = acc[ma][nb][h2 * 2], y = acc[ma][nb][h2 * 2 + 1];
                s += x * x + y * y;
            }
            s += __shfl_xor_sync(0xffffffffu, s, 1);
            s += __shfl_xor_sync(0xffffffffu, s, 2);
            ssq[ma][h2] = s;
        }
    __syncthreads();
    if ((lane & 3) == 0) {
        #pragma unroll
        for (int ma = 0; ma < 4; ma++)
            #pragma unroll
            for (int h2 = 0; h2 < 2; h2++)
                sred[wid * 64 + ma * 16 + h2 * 8 + g] = ssq[ma][h2];
    }
    __syncthreads();
    #pragma unroll
    for (int ma = 0; ma < 4; ma++)
        #pragma unroll
        for (int h2 = 0; h2 < 2; h2++) {
            int r = ma * 16 + h2 * 8 + g;
            float tot = sred[(wid & ~1) * 64 + r] + sred[((wid & ~1) + 1) * 64 + r];
            float rn = 1.f / fmaxf(sqrtf(tot), 1e-12f);
            int m = bm + warpM * 64 + r;
            #pragma unroll
            for (int nb = 0; nb < 4; nb++) {
                int n = bn + warpN * 32 + nb * 8 + t2;
                float v0 = acc[ma][nb][h2 * 2] * rn;
                float v1 = acc[ma][nb][h2 * 2 + 1] * rn;
                if (isQ) {
                    int bt = m >> 8, lq = m & 255;
                    int h = n >> 6, d = n & 63;
                    *(unsigned short*)&g_qh8[(((size_t)(bt * 8 + h)) * 256 + lq) * 64 + d] =
                        pk8(v0 * 4.f, v1 * 4.f);
                } else {
                    int bt = m >> 9, lk = m & 511;
                    int h = (n >> 6) & 7, d = n & 63;
                    if (n < 512) {
                        *(unsigned short*)&g_kh8[(((size_t)(bt * 8 + h)) * 512 + lk) * 64 + d] =
                            pk8(v0 * 4.f, v1 * 4.f);
                    } else {
                        *(unsigned*)&g_vh[(((size_t)(bt * 8 + h)) * 512 + lk) * 64 + d] = pk(v0, v1);
                    }
                }
            }
        }
}

// ---------------------------------------------------------------------------
// Output GEMM (bf16, proven): CTA 128x128, BK=64, 8 warps 2Mx4N.
// ---------------------------------------------------------------------------
__global__ __launch_bounds__(256, 2)
void out_gemm(const float* __restrict__ bias,
              const float* __restrict__ shortcut,
              float* __restrict__ out)
{
    extern __shared__ uint8_t dsm8[];
    const uint32_t smBase = smem_u32(dsm8);

    const int tid   = threadIdx.x;
    const int lane  = tid & 31;
    const int wid   = tid >> 5;
    const int warpM = wid >> 2;
    const int warpN = wid & 3;
    const int g     = lane >> 2;
    const int t2    = (lane & 3) * 2;
    const int lr    = lane & 15;
    const int lc    = lane >> 4;
    const int bm    = blockIdx.y * 128;
    const int bn    = blockIdx.x * 128;

    const bf16* A = g_xm;
    const bf16* W = g_wm;

    const int lrow = tid >> 3;
    const int lcc  = tid & 7;
    const bf16* srcA[4];
    const bf16* srcB[4];
    uint32_t dstOff[4];
    #pragma unroll
    for (int it = 0; it < 4; it++) {
        int row = lrow + it * 32;
        srcA[it] = A + (size_t)(bm + row) * CDIM + lcc * 8;
        srcB[it] = W + (size_t)(bn + row) * CDIM + lcc * 8;
        dstOff[it] = (uint32_t)(row * 144 + lcc * 16);
    }

    const uint32_t aoff = (uint32_t)((warpM * 64 + lr) * 144 + lc * 16);
    const uint32_t boff = (uint32_t)((warpN * 32 + lr) * 144 + lc * 16) + 18432;

    auto load_tile = [&](int t, int stage) {
        const uint32_t st = smBase + stage * GSTAGE;
        const int koff = t * 64;
        #pragma unroll
        for (int it = 0; it < 4; it++)
            cp_async16(st + dstOff[it], srcA[it] + koff);
        #pragma unroll
        for (int it = 0; it < 4; it++)
            cp_async16(st + 18432 + dstOff[it], srcB[it] + koff);
    };

    float acc[4][4][4] = {};

    load_tile(0, 0); cp_commit();
    load_tile(1, 1); cp_commit();

    #pragma unroll
    for (int t = 0; t < 8; t++) {
        cp_wait<1>();
        __syncthreads();
        if (t + 2 < 8) load_tile(t + 2, (t + 2) % 3);
        cp_commit();

        const uint32_t sa = smBase + (t % 3) * GSTAGE;
        #pragma unroll
        for (int ks = 0; ks < 4; ks++) {
            const int ko2 = ks * 32;
            unsigned af[4][4], bfm[2][4];
            #pragma unroll
            for (int ma = 0; ma < 4; ma++)
                ldm_x4(af[ma], sa + aoff + ma * 16 * 144 + ko2);
            #pragma unroll
            for (int p = 0; p < 2; p++)
                ldm_x4(bfm[p], sa + boff + p * 16 * 144 + ko2);
            #pragma unroll
            for (int ma = 0; ma < 4; ma++)
                #pragma unroll
                for (int nb = 0; nb < 4; nb++)
                    mma16816(acc[ma][nb], af[ma],
                             bfm[nb >> 1][nb & 1], bfm[nb >> 1][2 + (nb & 1)]);
        }
    }

    float2 bv[4];
    #pragma unroll
    for (int nb = 0; nb < 4; nb++)
        bv[nb] = *(const float2*)&bias[bn + warpN * 32 + nb * 8 + t2];

    #pragma unroll
    for (int ma = 0; ma < 4; ma++)
        #pragma unroll
        for (int h2 = 0; h2 < 2; h2++) {
            int m = bm + warpM * 64 + ma * 16 + h2 * 8 + g;
            #pragma unroll
            for (int nb = 0; nb < 4; nb++) {
                int n = bn + warpN * 32 + nb * 8 + t2;
                float2 s = *(const float2*)&shortcut[(size_t)m * CDIM + n];
                float2 o;
                o.x = acc[ma][nb][h2 * 2 + 0] + bv[nb].x + s.x;
                o.y = acc[ma][nb][h2 * 2 + 1] + bv[nb].y + s.y;
                *(float2*)&out[(size_t)m * CDIM + n] = o;
            }
        }
}

// ---------------------------------------------------------------------------
// Attention: fp8 QK^T (Q/K e4m3 x4-prescaled), bf16 PV (LDSM_T).
// block = (128 q-rows, h, bt), 8 warps, warp 16q x 64k, per-16-key streaming.
// smem: Qs fp8 128x80 (10240) | K fp8 3x(64x80)=15360 | V bf16 3x9216=27648.
// ---------------------------------------------------------------------------
#define ASMEM 53248

__global__ __launch_bounds__(256, 2)
void attn_mixed()
{
    extern __shared__ uint8_t dsm8[];
    const uint32_t smQ = smem_u32(dsm8);
    const uint32_t smK = smQ + 10240;
    const uint32_t smV = smK + 15360;

    const int tid  = threadIdx.x;
    const int lane = tid & 31;
    const int wid  = tid >> 5;
    const int g    = lane >> 2;
    const int t2   = (lane & 3) * 2;
    const int lr   = lane & 15;
    const int lc   = lane >> 4;
    const int qt   = blockIdx.x;
    const int h    = blockIdx.y;
    const int bt   = blockIdx.z;

    const uint8_t* Qg = g_qh8 + (((size_t)(bt * 8 + h)) * 256 + qt * 128) * 64;
    const uint8_t* Kg = g_kh8 + ((size_t)(bt * 8 + h)) * 512 * 64;
    const bf16*    Vg = g_vh  + ((size_t)(bt * 8 + h)) * 512 * 64;

    auto load_kv = [&](int t) {
        const int stage = t % 3;
        const uint32_t kb = smK + stage * 5120;
        const uint32_t vb = smV + stage * 9216;
        // K: 64 rows x 64B = 256 chunks
        {
            int row = tid >> 2, cc = tid & 3;
            cp_async16(kb + row * 80 + cc * 16, Kg + (size_t)(t * 64 + row) * 64 + cc * 16);
        }
        // V: 64 rows x 128B = 512 chunks
        #pragma unroll
        for (int it = 0; it < 2; it++) {
            int c = tid + it * 256;
            int row = c >> 3, cc = c & 7;
            cp_async16(vb + row * 144 + cc * 16, Vg + (size_t)(t * 64 + row) * 64 + cc * 8);
        }
    };

    load_kv(0); cp_commit();
    load_kv(1); cp_commit();

    // Q tile 128x64B fp8 -> smem (stride 80B)
    #pragma unroll
    for (int it = 0; it < 2; it++) {
        int idx = tid + it * 256;
        int row = idx >> 2, cc = idx & 3;
        *(uint4*)(dsm8 + row * 80 + cc * 16) = *(const uint4*)(Qg + (size_t)row * 64 + cc * 16);
    }
    __syncthreads();

    // Q fragments: 2 per warp (k-bytes 0-31, 32-63)
    unsigned qf[2][4];
    {
        const uint32_t qo = smQ + (uint32_t)((wid * 16 + lr) * 80 + lc * 16);
        ldm_x4(qf[0], qo);
        ldm_x4(qf[1], qo + 32);
    }

    float oacc[8][4] = {};
    float lsum0 = 0.f, lsum1 = 0.f;
    // scores carry x16 from the x4 prescale of q and k: fold 1/16 into exp scale
    const float sc = 0.125f * 1.4426950408889634f / 16.0f;

    #pragma unroll
    for (int t = 0; t < 8; t++) {
        cp_wait<1>();
        __syncthreads();
        if (t + 2 < 8) load_kv(t + 2);
        cp_commit();

        const uint32_t kb = smK + (t % 3) * 5120;
        const uint32_t vb = smV + (t % 3) * 9216;

        #pragma unroll
        for (int p = 0; p < 4; p++) {
            float s0[4] = {}, s1[4] = {};
            #pragma unroll
            for (int ka = 0; ka < 2; ka++) {
                unsigned kf[4];
                ldm_x4(kf, kb + (p * 16 + lr) * 80 + lc * 16 + ka * 32);
                mma_f8(s0, qf[ka], kf[0], kf[2]);
                mma_f8(s1, qf[ka], kf[1], kf[3]);
            }
            #pragma unroll
            for (int i = 0; i < 4; i++) {
                float e0, e1;
                asm("ex2.approx.f32 %0, %1;" : "=f"(e0) : "f"(s0[i] * sc));
                asm("ex2.approx.f32 %0, %1;" : "=f"(e1) : "f"(s1[i] * sc));
                s0[i] = e0; s1[i] = e1;
            }
            lsum0 += s0[0] + s0[1] + s1[0] + s1[1];
            lsum1 += s0[2] + s0[3] + s1[2] + s1[3];

            unsigned pf[4];
            pf[0] = pk(s0[0], s0[1]);
            pf[1] = pk(s0[2], s0[3]);
            pf[2] = pk(s1[0], s1[1]);
            pf[3] = pk(s1[2], s1[3]);

            #pragma unroll
            for (int d = 0; d < 4; d++) {
                unsigned vf[4];
                ldm_x4_t(vf, vb + (p * 16 + lr) * 144 + lc * 16 + d * 32);
                mma16816(oacc[2 * d + 0], pf, vf[0], vf[1]);
                mma16816(oacc[2 * d + 1], pf, vf[2], vf[3]);
            }
        }
    }

    lsum0 += __shfl_xor_sync(0xffffffffu, lsum0, 1);
    lsum0 += __shfl_xor_sync(0xffffffffu, lsum0, 2);
    lsum1 += __shfl_xor_sync(0xffffffffu, lsum1, 1);
    lsum1 += __shfl_xor_sync(0xffffffffu, lsum1, 2);
    const float rl0 = 1.f / lsum0, rl1 = 1.f / lsum1;

    bf16* Og = g_xm + ((size_t)bt * 256 + qt * 128) * 512 + h * 64;
    const int r0 = wid * 16 + g;
    #pragma unroll
    for (int nb = 0; nb < 8; nb++) {
        int n = nb * 8 + t2;
        *(unsigned*)&Og[(size_t)r0 * 512 + n]       = pk(oacc[nb][0] * rl0, oacc[nb][1] * rl0);
        *(unsigned*)&Og[(size_t)(r0 + 8) * 512 + n] = pk(oacc[nb][2] * rl1, oacc[nb][3] * rl1);
    }
}

// ---------------------------------------------------------------------------
extern "C" void kernel_launch(void* const* d_in, const int* in_sizes, int n_in,
                              void* d_out, int out_size)
{
    const float* q   = (const float*)d_in[0];
    const float* kv  = (const float*)d_in[1];
    const float* Wq  = (const float*)d_in[2];
    const float* bq  = (const float*)d_in[3];
    const float* Wkv = (const float*)d_in[4];
    const float* bkv = (const float*)d_in[5];
    const float* Wm  = (const float*)d_in[6];
    const float* bm  = (const float*)d_in[7];
    float* out = (float*)d_out;

    cudaFuncSetAttribute(proj_f8,   cudaFuncAttributeMaxDynamicSharedMemorySize, GSMEM);
    cudaFuncSetAttribute(out_gemm,  cudaFuncAttributeMaxDynamicSharedMemorySize, GSMEM);
    cudaFuncSetAttribute(attn_mixed, cudaFuncAttributeMaxDynamicSharedMemorySize, ASMEM);

    convert_all<<<ALL8 / 256, 256>>>(q, kv, Wq, Wkv, Wm);

    // merged Q+KV projections: 512 + 2048 CTAs
    proj_f8<<<2560, 256, GSMEM>>>(bq, bkv);
    attn_mixed<<<dim3(2, 8, 64), 256, ASMEM>>>();
    out_gemm<<<dim3(4, 128), 256, GSMEM>>>(bm, q, out);
}

// round 14
// speedup vs baseline: 1.1068x; 1.0073x over previous
#include <cuda_runtime.h>
#include <cuda_bf16.h>
#include <math.h>
#include <stdint.h>

#define BT_N 64
#define LQ   256
#define LK   512
#define CDIM 512
#define NH   8
#define HD   64

typedef __nv_bfloat16 bf16;

// ---- device scratch ----
__device__ uint8_t g_qf8 [(size_t)16384 * 512];
__device__ uint8_t g_kvf8[(size_t)32768 * 512];
__device__ uint8_t g_wqf8 [512 * 512];
__device__ uint8_t g_wkvf8[1024 * 512];
__device__ uint8_t g_wmf8 [512 * 512];                    // fp8, x32 prescale
__device__ uint8_t g_qh8 [(size_t)BT_N * NH * LQ * HD];   // fp8, x4 prescale
__device__ uint8_t g_kh8 [(size_t)BT_N * NH * LK * HD];   // fp8, x4 prescale
__device__ bf16    g_vh  [(size_t)BT_N * NH * LK * HD];   // bf16 row-major
__device__ uint8_t g_xm8 [(size_t)BT_N * LQ * CDIM];      // fp8, x16 prescale

// ---------------------------------------------------------------------------
__device__ __forceinline__ unsigned pk(float lo, float hi) {
    unsigned r;
    asm("cvt.rn.bf16x2.f32 %0, %1, %2;" : "=r"(r) : "f"(hi), "f"(lo));
    return r;
}
__device__ __forceinline__ unsigned short pk8(float lo, float hi) {
    unsigned short r;
    asm("cvt.rn.satfinite.e4m3x2.f32 %0, %1, %2;" : "=h"(r) : "f"(hi), "f"(lo));
    return r;
}
__device__ __forceinline__ uint32_t smem_u32(const void* p) {
    uint32_t a;
    asm("{ .reg .u64 t; cvta.to.shared.u64 t, %1; cvt.u32.u64 %0, t; }" : "=r"(a) : "l"(p));
    return a;
}
__device__ __forceinline__ void cp_async16(uint32_t dst, const void* src) {
    asm volatile("cp.async.cg.shared.global [%0], [%1], 16;" :: "r"(dst), "l"(src));
}
__device__ __forceinline__ void cp_commit() { asm volatile("cp.async.commit_group;" ::: "memory"); }
template<int N> __device__ __forceinline__ void cp_wait() { asm volatile("cp.async.wait_group %0;" :: "n"(N) : "memory"); }

__device__ __forceinline__ void ldm_x4(unsigned* r, uint32_t addr) {
    asm volatile("ldmatrix.sync.aligned.m8n8.x4.shared.b16 {%0,%1,%2,%3}, [%4];"
                 : "=r"(r[0]), "=r"(r[1]), "=r"(r[2]), "=r"(r[3]) : "r"(addr));
}
__device__ __forceinline__ void ldm_x4_t(unsigned* r, uint32_t addr) {
    asm volatile("ldmatrix.sync.aligned.m8n8.x4.trans.shared.b16 {%0,%1,%2,%3}, [%4];"
                 : "=r"(r[0]), "=r"(r[1]), "=r"(r[2]), "=r"(r[3]) : "r"(addr));
}

__device__ __forceinline__ void mma16816(float* d, const unsigned* a, unsigned b0, unsigned b1) {
    asm volatile(
        "mma.sync.aligned.m16n8k16.row.col.f32.bf16.bf16.f32 "
        "{%0,%1,%2,%3},{%4,%5,%6,%7},{%8,%9},{%0,%1,%2,%3};"
        : "+f"(d[0]), "+f"(d[1]), "+f"(d[2]), "+f"(d[3])
        : "r"(a[0]), "r"(a[1]), "r"(a[2]), "r"(a[3]), "r"(b0), "r"(b1));
}
__device__ __forceinline__ void mma_f8(float* d, const unsigned* a, unsigned b0, unsigned b1) {
    asm volatile(
        "mma.sync.aligned.m16n8k32.row.col.f32.e4m3.e4m3.f32 "
        "{%0,%1,%2,%3},{%4,%5,%6,%7},{%8,%9},{%0,%1,%2,%3};"
        : "+f"(d[0]), "+f"(d[1]), "+f"(d[2]), "+f"(d[3])
        : "r"(a[0]), "r"(a[1]), "r"(a[2]), "r"(a[3]), "r"(b0), "r"(b1));
}

// ---------------------------------------------------------------------------
// fp32 -> fp8 conversion (unit = 8 elements); weights prescaled x32
// ---------------------------------------------------------------------------
#define Q8   (16384 * 512 / 8)
#define KV8  (32768 * 512 / 8)
#define WQ8  (512 * 512 / 8)
#define WKV8 (1024 * 512 / 8)
#define WM8  (512 * 512 / 8)
#define ALL8 (Q8 + KV8 + WQ8 + WKV8 + WM8)

__device__ __forceinline__ void conv8_f8(const float* src, uint8_t* dst, int i, float s) {
    float4 a = ((const float4*)src)[2 * i];
    float4 b = ((const float4*)src)[2 * i + 1];
    unsigned short p0 = pk8(a.x * s, a.y * s), p1 = pk8(a.z * s, a.w * s);
    unsigned short p2 = pk8(b.x * s, b.y * s), p3 = pk8(b.z * s, b.w * s);
    ((uint2*)dst)[i] = make_uint2((unsigned)p0 | ((unsigned)p1 << 16),
                                  (unsigned)p2 | ((unsigned)p3 << 16));
}

__global__ __launch_bounds__(256)
void convert_all(const float* __restrict__ q, const float* __restrict__ kv,
                 const float* __restrict__ wq, const float* __restrict__ wkv,
                 const float* __restrict__ wm) {
    int i = blockIdx.x * blockDim.x + threadIdx.x;
    if (i < Q8)                          conv8_f8(q,   g_qf8,   i, 1.0f);
    else if (i < Q8 + KV8)               conv8_f8(kv,  g_kvf8,  i - Q8, 1.0f);
    else if (i < Q8 + KV8 + WQ8)         conv8_f8(wq,  g_wqf8,  i - Q8 - KV8, 32.0f);
    else if (i < Q8 + KV8 + WQ8 + WKV8)  conv8_f8(wkv, g_wkvf8, i - Q8 - KV8 - WQ8, 32.0f);
    else                                 conv8_f8(wm,  g_wmf8,  i - Q8 - KV8 - WQ8 - WKV8, 32.0f);
}

// ---------------------------------------------------------------------------
// Merged FP8 projection GEMM: blocks [0,512) = Q proj, [512,2560) = KV proj.
// CTA 128x128, BK=128B, 3-stage cp.async, 8 warps 2Mx4N, 144B row stride.
// ---------------------------------------------------------------------------
#define GSTAGE 36864
#define GSMEM  (3 * GSTAGE)

__global__ __launch_bounds__(256, 2)
void proj_f8(const float* __restrict__ bq, const float* __restrict__ bkv)
{
    extern __shared__ uint8_t dsm8[];
    __shared__ float sred[512];
    const uint32_t smBase = smem_u32(dsm8);

    const int tid   = threadIdx.x;
    const int lane  = tid & 31;
    const int wid   = tid >> 5;
    const int warpM = wid >> 2;
    const int warpN = wid & 3;
    const int g     = lane >> 2;
    const int t2    = (lane & 3) * 2;
    const int lr    = lane & 15;
    const int lc    = lane >> 4;

    const bool isQ = blockIdx.x < 512;
    int bm, bn;
    const uint8_t *A, *W;
    const float* bias;
    if (isQ) {
        int b = blockIdx.x;
        bn = (b & 3) * 128; bm = (b >> 2) * 128;
        A = g_qf8;  W = g_wqf8;  bias = bq;
    } else {
        int b = blockIdx.x - 512;
        bn = (b & 7) * 128; bm = (b >> 3) * 128;
        A = g_kvf8; W = g_wkvf8; bias = bkv;
    }

    const int lrow = tid >> 3;
    const int lcc  = tid & 7;
    const uint8_t* srcA[4];
    const uint8_t* srcB[4];
    uint32_t dstOff[4];
    #pragma unroll
    for (int it = 0; it < 4; it++) {
        int row = lrow + it * 32;
        srcA[it] = A + (size_t)(bm + row) * CDIM + lcc * 16;
        srcB[it] = W + (size_t)(bn + row) * CDIM + lcc * 16;
        dstOff[it] = (uint32_t)(row * 144 + lcc * 16);
    }

    const uint32_t aoff = (uint32_t)((warpM * 64 + lr) * 144 + lc * 16);
    const uint32_t boff = (uint32_t)((warpN * 32 + lr) * 144 + lc * 16) + 18432;

    auto load_tile = [&](int t, int stage) {
        const uint32_t st = smBase + stage * GSTAGE;
        const int koff = t * 128;
        #pragma unroll
        for (int it = 0; it < 4; it++)
            cp_async16(st + dstOff[it], srcA[it] + koff);
        #pragma unroll
        for (int it = 0; it < 4; it++)
            cp_async16(st + 18432 + dstOff[it], srcB[it] + koff);
    };

    float acc[4][4][4] = {};

    load_tile(0, 0); cp_commit();
    load_tile(1, 1); cp_commit();

    #pragma unroll
    for (int t = 0; t < 4; t++) {
        cp_wait<1>();
        __syncthreads();
        if (t + 2 < 4) load_tile(t + 2, (t + 2) % 3);
        cp_commit();

        const uint32_t sa = smBase + (t % 3) * GSTAGE;
        #pragma unroll
        for (int ks = 0; ks < 4; ks++) {
            const int ko2 = ks * 32;
            unsigned af[4][4], bfm[2][4];
            #pragma unroll
            for (int ma = 0; ma < 4; ma++)
                ldm_x4(af[ma], sa + aoff + ma * 16 * 144 + ko2);
            #pragma unroll
            for (int p = 0; p < 2; p++)
                ldm_x4(bfm[p], sa + boff + p * 16 * 144 + ko2);
            #pragma unroll
            for (int ma = 0; ma < 4; ma++)
                #pragma unroll
                for (int nb = 0; nb < 4; nb++)
                    mma_f8(acc[ma][nb], af[ma],
                           bfm[nb >> 1][nb & 1], bfm[nb >> 1][2 + (nb & 1)]);
        }
    }

    float2 bv[4];
    #pragma unroll
    for (int nb = 0; nb < 4; nb++)
        bv[nb] = *(const float2*)&bias[bn + warpN * 32 + nb * 8 + t2];
    #pragma unroll
    for (int ma = 0; ma < 4; ma++)
        #pragma unroll
        for (int nb = 0; nb < 4; nb++) {
            acc[ma][nb][0] = acc[ma][nb][0] * 0.03125f + bv[nb].x;
            acc[ma][nb][1] = acc[ma][nb][1] * 0.03125f + bv[nb].y;
            acc[ma][nb][2] = acc[ma][nb][2] * 0.03125f + bv[nb].x;
            acc[ma][nb][3] = acc[ma][nb][3] * 0.03125f + bv[nb].y;
        }

    float ssq[4][2];
    #pragma unroll
    for (int ma = 0; ma < 4; ma++)
        #pragma unroll
        for (int h2 = 0; h2 < 2; h2++) {
            float s = 0.f;
            #pragma unroll
            for (int nb = 0; nb < 4; nb++) {
                float x = acc[ma][nb][h2 * 2], y = acc[ma][nb][h2 * 2 + 1];
                s += x * x + y * y;
            }
            s += __shfl_xor_sync(0xffffffffu, s, 1);
            s += __shfl_xor_sync(0xffffffffu, s, 2);
            ssq[ma][h2] = s;
        }
    __syncthreads();
    if ((lane & 3) == 0) {
        #pragma unroll
        for (int ma = 0; ma < 4; ma++)
            #pragma unroll
            for (int h2 = 0; h2 < 2; h2++)
                sred[wid * 64 + ma * 16 + h2 * 8 + g] = ssq[ma][h2];
    }
    __syncthreads();
    #pragma unroll
    for (int ma = 0; ma < 4; ma++)
        #pragma unroll
        for (int h2 = 0; h2 < 2; h2++) {
            int r = ma * 16 + h2 * 8 + g;
            float tot = sred[(wid & ~1) * 64 + r] + sred[((wid & ~1) + 1) * 64 + r];
            float rn = 1.f / fmaxf(sqrtf(tot), 1e-12f);
            int m = bm + warpM * 64 + r;
            #pragma unroll
            for (int nb = 0; nb < 4; nb++) {
                int n = bn + warpN * 32 + nb * 8 + t2;
                float v0 = acc[ma][nb][h2 * 2] * rn;
                float v1 = acc[ma][nb][h2 * 2 + 1] * rn;
                if (isQ) {
                    int bt = m >> 8, lq = m & 255;
                    int h = n >> 6, d = n & 63;
                    *(unsigned short*)&g_qh8[(((size_t)(bt * 8 + h)) * 256 + lq) * 64 + d] =
                        pk8(v0 * 4.f, v1 * 4.f);
                } else {
                    int bt = m >> 9, lk = m & 511;
                    int h = (n >> 6) & 7, d = n & 63;
                    if (n < 512) {
                        *(unsigned short*)&g_kh8[(((size_t)(bt * 8 + h)) * 512 + lk) * 64 + d] =
                            pk8(v0 * 4.f, v1 * 4.f);
                    } else {
                        *(unsigned*)&g_vh[(((size_t)(bt * 8 + h)) * 512 + lk) * 64 + d] = pk(v0, v1);
                    }
                }
            }
        }
}

// ---------------------------------------------------------------------------
// FP8 output GEMM: xm(fp8 x16) @ Wm(fp8 x32)^T * (1/512) + bias + shortcut.
// Same mainloop as proj_f8 (proven).
// ---------------------------------------------------------------------------
__global__ __launch_bounds__(256, 2)
void out_f8(const float* __restrict__ bias,
            const float* __restrict__ shortcut,
            float* __restrict__ out)
{
    extern __shared__ uint8_t dsm8[];
    const uint32_t smBase = smem_u32(dsm8);

    const int tid   = threadIdx.x;
    const int lane  = tid & 31;
    const int wid   = tid >> 5;
    const int warpM = wid >> 2;
    const int warpN = wid & 3;
    const int g     = lane >> 2;
    const int t2    = (lane & 3) * 2;
    const int lr    = lane & 15;
    const int lc    = lane >> 4;
    const int bm    = blockIdx.y * 128;
    const int bn    = blockIdx.x * 128;

    const uint8_t* A = g_xm8;
    const uint8_t* W = g_wmf8;

    const int lrow = tid >> 3;
    const int lcc  = tid & 7;
    const uint8_t* srcA[4];
    const uint8_t* srcB[4];
    uint32_t dstOff[4];
    #pragma unroll
    for (int it = 0; it < 4; it++) {
        int row = lrow + it * 32;
        srcA[it] = A + (size_t)(bm + row) * CDIM + lcc * 16;
        srcB[it] = W + (size_t)(bn + row) * CDIM + lcc * 16;
        dstOff[it] = (uint32_t)(row * 144 + lcc * 16);
    }

    const uint32_t aoff = (uint32_t)((warpM * 64 + lr) * 144 + lc * 16);
    const uint32_t boff = (uint32_t)((warpN * 32 + lr) * 144 + lc * 16) + 18432;

    auto load_tile = [&](int t, int stage) {
        const uint32_t st = smBase + stage * GSTAGE;
        const int koff = t * 128;
        #pragma unroll
        for (int it = 0; it < 4; it++)
            cp_async16(st + dstOff[it], srcA[it] + koff);
        #pragma unroll
        for (int it = 0; it < 4; it++)
            cp_async16(st + 18432 + dstOff[it], srcB[it] + koff);
    };

    float acc[4][4][4] = {};

    load_tile(0, 0); cp_commit();
    load_tile(1, 1); cp_commit();

    #pragma unroll
    for (int t = 0; t < 4; t++) {
        cp_wait<1>();
        __syncthreads();
        if (t + 2 < 4) load_tile(t + 2, (t + 2) % 3);
        cp_commit();

        const uint32_t sa = smBase + (t % 3) * GSTAGE;
        #pragma unroll
        for (int ks = 0; ks < 4; ks++) {
            const int ko2 = ks * 32;
            unsigned af[4][4], bfm[2][4];
            #pragma unroll
            for (int ma = 0; ma < 4; ma++)
                ldm_x4(af[ma], sa + aoff + ma * 16 * 144 + ko2);
            #pragma unroll
            for (int p = 0; p < 2; p++)
                ldm_x4(bfm[p], sa + boff + p * 16 * 144 + ko2);
            #pragma unroll
            for (int ma = 0; ma < 4; ma++)
                #pragma unroll
                for (int nb = 0; nb < 4; nb++)
                    mma_f8(acc[ma][nb], af[ma],
                           bfm[nb >> 1][nb & 1], bfm[nb >> 1][2 + (nb & 1)]);
        }
    }

    const float s = 1.0f / 512.0f;   // undo x16 (xm) * x32 (wm)
    float2 bv[4];
    #pragma unroll
    for (int nb = 0; nb < 4; nb++)
        bv[nb] = *(const float2*)&bias[bn + warpN * 32 + nb * 8 + t2];

    #pragma unroll
    for (int ma = 0; ma < 4; ma++)
        #pragma unroll
        for (int h2 = 0; h2 < 2; h2++) {
            int m = bm + warpM * 64 + ma * 16 + h2 * 8 + g;
            #pragma unroll
            for (int nb = 0; nb < 4; nb++) {
                int n = bn + warpN * 32 + nb * 8 + t2;
                float2 sc2 = *(const float2*)&shortcut[(size_t)m * CDIM + n];
                float2 o;
                o.x = acc[ma][nb][h2 * 2 + 0] * s + bv[nb].x + sc2.x;
                o.y = acc[ma][nb][h2 * 2 + 1] * s + bv[nb].y + sc2.y;
                *(float2*)&out[(size_t)m * CDIM + n] = o;
            }
        }
}

// ---------------------------------------------------------------------------
// Attention: fp8 QK^T, bf16 PV (LDSM_T); xm stored fp8 (x16).
// block = (128 q-rows, h, bt), 8 warps, warp 16q x 64k, per-16-key streaming.
// ---------------------------------------------------------------------------
#define ASMEM 53248

__global__ __launch_bounds__(256, 2)
void attn_mixed()
{
    extern __shared__ uint8_t dsm8[];
    const uint32_t smQ = smem_u32(dsm8);
    const uint32_t smK = smQ + 10240;
    const uint32_t smV = smK + 15360;

    const int tid  = threadIdx.x;
    const int lane = tid & 31;
    const int wid  = tid >> 5;
    const int g    = lane >> 2;
    const int t2   = (lane & 3) * 2;
    const int lr   = lane & 15;
    const int lc   = lane >> 4;
    const int qt   = blockIdx.x;
    const int h    = blockIdx.y;
    const int bt   = blockIdx.z;

    const uint8_t* Qg = g_qh8 + (((size_t)(bt * 8 + h)) * 256 + qt * 128) * 64;
    const uint8_t* Kg = g_kh8 + ((size_t)(bt * 8 + h)) * 512 * 64;
    const bf16*    Vg = g_vh  + ((size_t)(bt * 8 + h)) * 512 * 64;

    auto load_kv = [&](int t) {
        const int stage = t % 3;
        const uint32_t kb = smK + stage * 5120;
        const uint32_t vb = smV + stage * 9216;
        {
            int row = tid >> 2, cc = tid & 3;
            cp_async16(kb + row * 80 + cc * 16, Kg + (size_t)(t * 64 + row) * 64 + cc * 16);
        }
        #pragma unroll
        for (int it = 0; it < 2; it++) {
            int c = tid + it * 256;
            int row = c >> 3, cc = c & 7;
            cp_async16(vb + row * 144 + cc * 16, Vg + (size_t)(t * 64 + row) * 64 + cc * 8);
        }
    };

    load_kv(0); cp_commit();
    load_kv(1); cp_commit();

    #pragma unroll
    for (int it = 0; it < 2; it++) {
        int idx = tid + it * 256;
        int row = idx >> 2, cc = idx & 3;
        *(uint4*)(dsm8 + row * 80 + cc * 16) = *(const uint4*)(Qg + (size_t)row * 64 + cc * 16);
    }
    __syncthreads();

    unsigned qf[2][4];
    {
        const uint32_t qo = smQ + (uint32_t)((wid * 16 + lr) * 80 + lc * 16);
        ldm_x4(qf[0], qo);
        ldm_x4(qf[1], qo + 32);
    }

    float oacc[8][4] = {};
    float lsum0 = 0.f, lsum1 = 0.f;
    const float sc = 0.125f * 1.4426950408889634f / 16.0f;

    #pragma unroll
    for (int t = 0; t < 8; t++) {
        cp_wait<1>();
        __syncthreads();
        if (t + 2 < 8) load_kv(t + 2);
        cp_commit();

        const uint32_t kb = smK + (t % 3) * 5120;
        const uint32_t vb = smV + (t % 3) * 9216;

        #pragma unroll
        for (int p = 0; p < 4; p++) {
            float s0[4] = {}, s1[4] = {};
            #pragma unroll
            for (int ka = 0; ka < 2; ka++) {
                unsigned kf[4];
                ldm_x4(kf, kb + (p * 16 + lr) * 80 + lc * 16 + ka * 32);
                mma_f8(s0, qf[ka], kf[0], kf[2]);
                mma_f8(s1, qf[ka], kf[1], kf[3]);
            }
            #pragma unroll
            for (int i = 0; i < 4; i++) {
                float e0, e1;
                asm("ex2.approx.f32 %0, %1;" : "=f"(e0) : "f"(s0[i] * sc));
                asm("ex2.approx.f32 %0, %1;" : "=f"(e1) : "f"(s1[i] * sc));
                s0[i] = e0; s1[i] = e1;
            }
            lsum0 += s0[0] + s0[1] + s1[0] + s1[1];
            lsum1 += s0[2] + s0[3] + s1[2] + s1[3];

            unsigned pf[4];
            pf[0] = pk(s0[0], s0[1]);
            pf[1] = pk(s0[2], s0[3]);
            pf[2] = pk(s1[0], s1[1]);
            pf[3] = pk(s1[2], s1[3]);

            #pragma unroll
            for (int d = 0; d < 4; d++) {
                unsigned vf[4];
                ldm_x4_t(vf, vb + (p * 16 + lr) * 144 + lc * 16 + d * 32);
                mma16816(oacc[2 * d + 0], pf, vf[0], vf[1]);
                mma16816(oacc[2 * d + 1], pf, vf[2], vf[3]);
            }
        }
    }

    lsum0 += __shfl_xor_sync(0xffffffffu, lsum0, 1);
    lsum0 += __shfl_xor_sync(0xffffffffu, lsum0, 2);
    lsum1 += __shfl_xor_sync(0xffffffffu, lsum1, 1);
    lsum1 += __shfl_xor_sync(0xffffffffu, lsum1, 2);
    const float rs0 = 16.0f / lsum0, rs1 = 16.0f / lsum1;   // x16 fp8 prescale

    uint8_t* Og = g_xm8 + ((size_t)bt * 256 + qt * 128) * 512 + h * 64;
    const int r0 = wid * 16 + g;
    #pragma unroll
    for (int nb = 0; nb < 8; nb++) {
        int n = nb * 8 + t2;
        *(unsigned short*)&Og[(size_t)r0 * 512 + n] =
            pk8(oacc[nb][0] * rs0, oacc[nb][1] * rs0);
        *(unsigned short*)&Og[(size_t)(r0 + 8) * 512 + n] =
            pk8(oacc[nb][2] * rs1, oacc[nb][3] * rs1);
    }
}

// ---------------------------------------------------------------------------
extern "C" void kernel_launch(void* const* d_in, const int* in_sizes, int n_in,
                              void* d_out, int out_size)
{
    const float* q   = (const float*)d_in[0];
    const float* kv  = (const float*)d_in[1];
    const float* Wq  = (const float*)d_in[2];
    const float* bq  = (const float*)d_in[3];
    const float* Wkv = (const float*)d_in[4];
    const float* bkv = (const float*)d_in[5];
    const float* Wm  = (const float*)d_in[6];
    const float* bm  = (const float*)d_in[7];
    float* out = (float*)d_out;

    cudaFuncSetAttribute(proj_f8,    cudaFuncAttributeMaxDynamicSharedMemorySize, GSMEM);
    cudaFuncSetAttribute(out_f8,     cudaFuncAttributeMaxDynamicSharedMemorySize, GSMEM);
    cudaFuncSetAttribute(attn_mixed, cudaFuncAttributeMaxDynamicSharedMemorySize, ASMEM);

    convert_all<<<ALL8 / 256, 256>>>(q, kv, Wq, Wkv, Wm);

    proj_f8<<<2560, 256, GSMEM>>>(bq, bkv);
    attn_mixed<<<dim3(2, 8, 64), 256, ASMEM>>>();
    out_f8<<<dim3(4, 128), 256, GSMEM>>>(bm, q, out);
}

// round 16
// speedup vs baseline: 1.1275x; 1.0187x over previous
#include <cuda_runtime.h>
#include <cuda_bf16.h>
#include <math.h>
#include <stdint.h>

#define BT_N 64
#define LQ   256
#define LK   512
#define CDIM 512
#define NH   8
#define HD   64

typedef __nv_bfloat16 bf16;

// ---- device scratch ----
__device__ uint8_t g_qf8 [(size_t)16384 * 512];
__device__ uint8_t g_kvf8[(size_t)32768 * 512];
__device__ uint8_t g_wqf8 [512 * 512];
__device__ uint8_t g_wkvf8[1024 * 512];
__device__ uint8_t g_wmf8 [512 * 512];                    // fp8, x32 prescale
__device__ uint8_t g_qh8 [(size_t)BT_N * NH * LQ * HD];   // fp8, x4 prescale
__device__ uint8_t g_kh8 [(size_t)BT_N * NH * LK * HD];   // fp8, x4 prescale
__device__ bf16    g_vh  [(size_t)BT_N * NH * LK * HD];   // bf16 row-major
__device__ uint8_t g_xm8 [(size_t)BT_N * LQ * CDIM];      // fp8, x16 prescale

// ---------------------------------------------------------------------------
__device__ __forceinline__ unsigned pk(float lo, float hi) {
    unsigned r;
    asm("cvt.rn.bf16x2.f32 %0, %1, %2;" : "=r"(r) : "f"(hi), "f"(lo));
    return r;
}
__device__ __forceinline__ unsigned short pk8(float lo, float hi) {
    unsigned short r;
    asm("cvt.rn.satfinite.e4m3x2.f32 %0, %1, %2;" : "=h"(r) : "f"(hi), "f"(lo));
    return r;
}
__device__ __forceinline__ uint32_t smem_u32(const void* p) {
    uint32_t a;
    asm("{ .reg .u64 t; cvta.to.shared.u64 t, %1; cvt.u32.u64 %0, t; }" : "=r"(a) : "l"(p));
    return a;
}
__device__ __forceinline__ void cp_async16(uint32_t dst, const void* src) {
    asm volatile("cp.async.cg.shared.global [%0], [%1], 16;" :: "r"(dst), "l"(src));
}
__device__ __forceinline__ void cp_commit() { asm volatile("cp.async.commit_group;" ::: "memory"); }
template<int N> __device__ __forceinline__ void cp_wait() { asm volatile("cp.async.wait_group %0;" :: "n"(N) : "memory"); }

__device__ __forceinline__ void ldm_x4(unsigned* r, uint32_t addr) {
    asm volatile("ldmatrix.sync.aligned.m8n8.x4.shared.b16 {%0,%1,%2,%3}, [%4];"
                 : "=r"(r[0]), "=r"(r[1]), "=r"(r[2]), "=r"(r[3]) : "r"(addr));
}
__device__ __forceinline__ void ldm_x4_t(unsigned* r, uint32_t addr) {
    asm volatile("ldmatrix.sync.aligned.m8n8.x4.trans.shared.b16 {%0,%1,%2,%3}, [%4];"
                 : "=r"(r[0]), "=r"(r[1]), "=r"(r[2]), "=r"(r[3]) : "r"(addr));
}

__device__ __forceinline__ void mma16816(float* d, const unsigned* a, unsigned b0, unsigned b1) {
    asm volatile(
        "mma.sync.aligned.m16n8k16.row.col.f32.bf16.bf16.f32 "
        "{%0,%1,%2,%3},{%4,%5,%6,%7},{%8,%9},{%0,%1,%2,%3};"
        : "+f"(d[0]), "+f"(d[1]), "+f"(d[2]), "+f"(d[3])
        : "r"(a[0]), "r"(a[1]), "r"(a[2]), "r"(a[3]), "r"(b0), "r"(b1));
}
__device__ __forceinline__ void mma_f8(float* d, const unsigned* a, unsigned b0, unsigned b1) {
    asm volatile(
        "mma.sync.aligned.m16n8k32.row.col.f32.e4m3.e4m3.f32 "
        "{%0,%1,%2,%3},{%4,%5,%6,%7},{%8,%9},{%0,%1,%2,%3};"
        : "+f"(d[0]), "+f"(d[1]), "+f"(d[2]), "+f"(d[3])
        : "r"(a[0]), "r"(a[1]), "r"(a[2]), "r"(a[3]), "r"(b0), "r"(b1));
}

// ---------------------------------------------------------------------------
// fp32 -> fp8 conversion (unit = 8 elements); weights prescaled x32
// ---------------------------------------------------------------------------
#define Q8   (16384 * 512 / 8)
#define KV8  (32768 * 512 / 8)
#define WQ8  (512 * 512 / 8)
#define WKV8 (1024 * 512 / 8)
#define WM8  (512 * 512 / 8)
#define ALL8 (Q8 + KV8 + WQ8 + WKV8 + WM8)

__device__ __forceinline__ void conv8_f8(const float* src, uint8_t* dst, int i, float s) {
    float4 a = ((const float4*)src)[2 * i];
    float4 b = ((const float4*)src)[2 * i + 1];
    unsigned short p0 = pk8(a.x * s, a.y * s), p1 = pk8(a.z * s, a.w * s);
    unsigned short p2 = pk8(b.x * s, b.y * s), p3 = pk8(b.z * s, b.w * s);
    ((uint2*)dst)[i] = make_uint2((unsigned)p0 | ((unsigned)p1 << 16),
                                  (unsigned)p2 | ((unsigned)p3 << 16));
}

__global__ __launch_bounds__(256)
void convert_all(const float* __restrict__ q, const float* __restrict__ kv,
                 const float* __restrict__ wq, const float* __restrict__ wkv,
                 const float* __restrict__ wm) {
    int i = blockIdx.x * blockDim.x + threadIdx.x;
    if (i < Q8)                          conv8_f8(q,   g_qf8,   i, 1.0f);
    else if (i < Q8 + KV8)               conv8_f8(kv,  g_kvf8,  i - Q8, 1.0f);
    else if (i < Q8 + KV8 + WQ8)         conv8_f8(wq,  g_wqf8,  i - Q8 - KV8, 32.0f);
    else if (i < Q8 + KV8 + WQ8 + WKV8)  conv8_f8(wkv, g_wkvf8, i - Q8 - KV8 - WQ8, 32.0f);
    else                                 conv8_f8(wm,  g_wmf8,  i - Q8 - KV8 - WQ8 - WKV8, 32.0f);
}

// ---------------------------------------------------------------------------
// Merged FP8 projection GEMM: blocks [0,512) = Q proj, [512,2560) = KV proj.
// CTA 128x128, BK=128B, 3-stage cp.async, 8 warps 2Mx4N, 144B row stride.
// ---------------------------------------------------------------------------
#define GSTAGE 36864
#define GSMEM  (3 * GSTAGE)

__global__ __launch_bounds__(256, 2)
void proj_f8(const float* __restrict__ bq, const float* __restrict__ bkv)
{
    extern __shared__ uint8_t dsm8[];
    __shared__ float sred[512];
    const uint32_t smBase = smem_u32(dsm8);

    const int tid   = threadIdx.x;
    const int lane  = tid & 31;
    const int wid   = tid >> 5;
    const int warpM = wid >> 2;
    const int warpN = wid & 3;
    const int g     = lane >> 2;
    const int t2    = (lane & 3) * 2;
    const int lr    = lane & 15;
    const int lc    = lane >> 4;

    const bool isQ = blockIdx.x < 512;
    int bm, bn;
    const uint8_t *A, *W;
    const float* bias;
    if (isQ) {
        int b = blockIdx.x;
        bn = (b & 3) * 128; bm = (b >> 2) * 128;
        A = g_qf8;  W = g_wqf8;  bias = bq;
    } else {
        int b = blockIdx.x - 512;
        bn = (b & 7) * 128; bm = (b >> 3) * 128;
        A = g_kvf8; W = g_wkvf8; bias = bkv;
    }

    const int lrow = tid >> 3;
    const int lcc  = tid & 7;
    const uint8_t* srcA[4];
    const uint8_t* srcB[4];
    uint32_t dstOff[4];
    #pragma unroll
    for (int it = 0; it < 4; it++) {
        int row = lrow + it * 32;
        srcA[it] = A + (size_t)(bm + row) * CDIM + lcc * 16;
        srcB[it] = W + (size_t)(bn + row) * CDIM + lcc * 16;
        dstOff[it] = (uint32_t)(row * 144 + lcc * 16);
    }

    const uint32_t aoff = (uint32_t)((warpM * 64 + lr) * 144 + lc * 16);
    const uint32_t boff = (uint32_t)((warpN * 32 + lr) * 144 + lc * 16) + 18432;

    auto load_tile = [&](int t, int stage) {
        const uint32_t st = smBase + stage * GSTAGE;
        const int koff = t * 128;
        #pragma unroll
        for (int it = 0; it < 4; it++)
            cp_async16(st + dstOff[it], srcA[it] + koff);
        #pragma unroll
        for (int it = 0; it < 4; it++)
            cp_async16(st + 18432 + dstOff[it], srcB[it] + koff);
    };

    float acc[4][4][4] = {};

    load_tile(0, 0); cp_commit();
    load_tile(1, 1); cp_commit();

    #pragma unroll
    for (int t = 0; t < 4; t++) {
        cp_wait<1>();
        __syncthreads();
        if (t + 2 < 4) load_tile(t + 2, (t + 2) % 3);
        cp_commit();

        const uint32_t sa = smBase + (t % 3) * GSTAGE;
        #pragma unroll
        for (int ks = 0; ks < 4; ks++) {
            const int ko2 = ks * 32;
            unsigned af[4][4], bfm[2][4];
            #pragma unroll
            for (int ma = 0; ma < 4; ma++)
                ldm_x4(af[ma], sa + aoff + ma * 16 * 144 + ko2);
            #pragma unroll
            for (int p = 0; p < 2; p++)
                ldm_x4(bfm[p], sa + boff + p * 16 * 144 + ko2);
            #pragma unroll
            for (int ma = 0; ma < 4; ma++)
                #pragma unroll
                for (int nb = 0; nb < 4; nb++)
                    mma_f8(acc[ma][nb], af[ma],
                           bfm[nb >> 1][nb & 1], bfm[nb >> 1][2 + (nb & 1)]);
        }
    }

    float2 bv[4];
    #pragma unroll
    for (int nb = 0; nb < 4; nb++)
        bv[nb] = *(const float2*)&bias[bn + warpN * 32 + nb * 8 + t2];
    #pragma unroll
    for (int ma = 0; ma < 4; ma++)
        #pragma unroll
        for (int nb = 0; nb < 4; nb++) {
            acc[ma][nb][0] = acc[ma][nb][0] * 0.03125f + bv[nb].x;
            acc[ma][nb][1] = acc[ma][nb][1] * 0.03125f + bv[nb].y;
            acc[ma][nb][2] = acc[ma][nb][2] * 0.03125f + bv[nb].x;
            acc[ma][nb][3] = acc[ma][nb][3] * 0.03125f + bv[nb].y;
        }

    float ssq[4][2];
    #pragma unroll
    for (int ma = 0; ma < 4; ma++)
        #pragma unroll
        for (int h2 = 0; h2 < 2; h2++) {
            float s = 0.f;
            #pragma unroll
            for (int nb = 0; nb < 4; nb++) {
                float x = acc[ma][nb][h2 * 2], y = acc[ma][nb][h2 * 2 + 1];
                s += x * x + y * y;
            }
            s += __shfl_xor_sync(0xffffffffu, s, 1);
            s += __shfl_xor_sync(0xffffffffu, s, 2);
            ssq[ma][h2] = s;
        }
    __syncthreads();
    if ((lane & 3) == 0) {
        #pragma unroll
        for (int ma = 0; ma < 4; ma++)
            #pragma unroll
            for (int h2 = 0; h2 < 2; h2++)
                sred[wid * 64 + ma * 16 + h2 * 8 + g] = ssq[ma][h2];
    }
    __syncthreads();
    #pragma unroll
    for (int ma = 0; ma < 4; ma++)
        #pragma unroll
        for (int h2 = 0; h2 < 2; h2++) {
            int r = ma * 16 + h2 * 8 + g;
            float tot = sred[(wid & ~1) * 64 + r] + sred[((wid & ~1) + 1) * 64 + r];
            float rn = 1.f / fmaxf(sqrtf(tot), 1e-12f);
            int m = bm + warpM * 64 + r;
            #pragma unroll
            for (int nb = 0; nb < 4; nb++) {
                int n = bn + warpN * 32 + nb * 8 + t2;
                float v0 = acc[ma][nb][h2 * 2] * rn;
                float v1 = acc[ma][nb][h2 * 2 + 1] * rn;
                if (isQ) {
                    int bt = m >> 8, lq = m & 255;
                    int h = n >> 6, d = n & 63;
                    *(unsigned short*)&g_qh8[(((size_t)(bt * 8 + h)) * 256 + lq) * 64 + d] =
                        pk8(v0 * 4.f, v1 * 4.f);
                } else {
                    int bt = m >> 9, lk = m & 511;
                    int h = (n >> 6) & 7, d = n & 63;
                    if (n < 512) {
                        *(unsigned short*)&g_kh8[(((size_t)(bt * 8 + h)) * 512 + lk) * 64 + d] =
                            pk8(v0 * 4.f, v1 * 4.f);
                    } else {
                        *(unsigned*)&g_vh[(((size_t)(bt * 8 + h)) * 512 + lk) * 64 + d] = pk(v0, v1);
                    }
                }
            }
        }
}

// ---------------------------------------------------------------------------
// FP8 output GEMM with pipelined shortcut prefetch:
// during the last mainloop iteration the 64KB fp32 shortcut tile is
// cp.async'd into the retired stage-1/2 smem (row stride 528B = 132 words
// = 4 mod 32 -> conflict-free epilogue reads). 128 rows x 32 chunks.
// ---------------------------------------------------------------------------
#define SHORT_OFF 36864

__global__ __launch_bounds__(256, 2)
void out_f8(const float* __restrict__ bias,
            const float* __restrict__ shortcut,
            float* __restrict__ out)
{
    extern __shared__ uint8_t dsm8[];
    const uint32_t smBase = smem_u32(dsm8);

    const int tid   = threadIdx.x;
    const int lane  = tid & 31;
    const int wid   = tid >> 5;
    const int warpM = wid >> 2;
    const int warpN = wid & 3;
    const int g     = lane >> 2;
    const int t2    = (lane & 3) * 2;
    const int lr    = lane & 15;
    const int lc    = lane >> 4;
    const int bm    = blockIdx.y * 128;
    const int bn    = blockIdx.x * 128;

    const uint8_t* A = g_xm8;
    const uint8_t* W = g_wmf8;

    const int lrow = tid >> 3;
    const int lcc  = tid & 7;
    const uint8_t* srcA[4];
    const uint8_t* srcB[4];
    uint32_t dstOff[4];
    #pragma unroll
    for (int it = 0; it < 4; it++) {
        int row = lrow + it * 32;
        srcA[it] = A + (size_t)(bm + row) * CDIM + lcc * 16;
        srcB[it] = W + (size_t)(bn + row) * CDIM + lcc * 16;
        dstOff[it] = (uint32_t)(row * 144 + lcc * 16);
    }

    const uint32_t aoff = (uint32_t)((warpM * 64 + lr) * 144 + lc * 16);
    const uint32_t boff = (uint32_t)((warpN * 32 + lr) * 144 + lc * 16) + 18432;

    auto load_tile = [&](int t, int stage) {
        const uint32_t st = smBase + stage * GSTAGE;
        const int koff = t * 128;
        #pragma unroll
        for (int it = 0; it < 4; it++)
            cp_async16(st + dstOff[it], srcA[it] + koff);
        #pragma unroll
        for (int it = 0; it < 4; it++)
            cp_async16(st + 18432 + dstOff[it], srcB[it] + koff);
    };

    float acc[4][4][4] = {};

    load_tile(0, 0); cp_commit();
    load_tile(1, 1); cp_commit();

    #pragma unroll
    for (int t = 0; t < 4; t++) {
        cp_wait<1>();
        __syncthreads();
        if (t + 2 < 4) {
            load_tile(t + 2, (t + 2) % 3);
        } else if (t == 3) {
            // prefetch shortcut 128x128 fp32 (512B/row = 32 x 16B chunks)
            #pragma unroll
            for (int it = 0; it < 16; it++) {
                int c   = tid + it * 256;     // 0..4095
                int row = c >> 5;             // 0..127
                int cc  = c & 31;             // 0..31
                cp_async16(smBase + SHORT_OFF + row * 528 + cc * 16,
                           shortcut + (size_t)(bm + row) * CDIM + bn + cc * 4);
            }
        }
        cp_commit();

        const uint32_t sa = smBase + (t % 3) * GSTAGE;
        #pragma unroll
        for (int ks = 0; ks < 4; ks++) {
            const int ko2 = ks * 32;
            unsigned af[4][4], bfm[2][4];
            #pragma unroll
            for (int ma = 0; ma < 4; ma++)
                ldm_x4(af[ma], sa + aoff + ma * 16 * 144 + ko2);
            #pragma unroll
            for (int p = 0; p < 2; p++)
                ldm_x4(bfm[p], sa + boff + p * 16 * 144 + ko2);
            #pragma unroll
            for (int ma = 0; ma < 4; ma++)
                #pragma unroll
                for (int nb = 0; nb < 4; nb++)
                    mma_f8(acc[ma][nb], af[ma],
                           bfm[nb >> 1][nb & 1], bfm[nb >> 1][2 + (nb & 1)]);
        }
    }

    cp_wait<0>();
    __syncthreads();

    const float s = 1.0f / 512.0f;   // undo x16 (xm) * x32 (wm)
    float2 bv[4];
    #pragma unroll
    for (int nb = 0; nb < 4; nb++)
        bv[nb] = *(const float2*)&bias[bn + warpN * 32 + nb * 8 + t2];

    #pragma unroll
    for (int ma = 0; ma < 4; ma++)
        #pragma unroll
        for (int h2 = 0; h2 < 2; h2++) {
            int ml = warpM * 64 + ma * 16 + h2 * 8 + g;       // local row
            int m  = bm + ml;
            #pragma unroll
            for (int nb = 0; nb < 4; nb++) {
                int nl = warpN * 32 + nb * 8 + t2;            // local col
                float2 sc2 = *(const float2*)(dsm8 + SHORT_OFF + ml * 528 + nl * 4);
                float2 o;
                o.x = acc[ma][nb][h2 * 2 + 0] * s + bv[nb].x + sc2.x;
                o.y = acc[ma][nb][h2 * 2 + 1] * s + bv[nb].y + sc2.y;
                *(float2*)&out[(size_t)m * CDIM + bn + nl] = o;
            }
        }
}

// ---------------------------------------------------------------------------
// Attention: fp8 QK^T, bf16 PV (LDSM_T); xm stored fp8 (x16).
// block = (128 q-rows, h, bt), 8 warps, warp 16q x 64k, per-16-key streaming.
// ---------------------------------------------------------------------------
#define ASMEM 53248

__global__ __launch_bounds__(256, 2)
void attn_mixed()
{
    extern __shared__ uint8_t dsm8[];
    const uint32_t smQ = smem_u32(dsm8);
    const uint32_t smK = smQ + 10240;
    const uint32_t smV = smK + 15360;

    const int tid  = threadIdx.x;
    const int lane = tid & 31;
    const int wid  = tid >> 5;
    const int g    = lane >> 2;
    const int t2   = (lane & 3) * 2;
    const int lr   = lane & 15;
    const int lc   = lane >> 4;
    const int qt   = blockIdx.x;
    const int h    = blockIdx.y;
    const int bt   = blockIdx.z;

    const uint8_t* Qg = g_qh8 + (((size_t)(bt * 8 + h)) * 256 + qt * 128) * 64;
    const uint8_t* Kg = g_kh8 + ((size_t)(bt * 8 + h)) * 512 * 64;
    const bf16*    Vg = g_vh  + ((size_t)(bt * 8 + h)) * 512 * 64;

    auto load_kv = [&](int t) {
        const int stage = t % 3;
        const uint32_t kb = smK + stage * 5120;
        const uint32_t vb = smV + stage * 9216;
        {
            int row = tid >> 2, cc = tid & 3;
            cp_async16(kb + row * 80 + cc * 16, Kg + (size_t)(t * 64 + row) * 64 + cc * 16);
        }
        #pragma unroll
        for (int it = 0; it < 2; it++) {
            int c = tid + it * 256;
            int row = c >> 3, cc = c & 7;
            cp_async16(vb + row * 144 + cc * 16, Vg + (size_t)(t * 64 + row) * 64 + cc * 8);
        }
    };

    load_kv(0); cp_commit();
    load_kv(1); cp_commit();

    #pragma unroll
    for (int it = 0; it < 2; it++) {
        int idx = tid + it * 256;
        int row = idx >> 2, cc = idx & 3;
        *(uint4*)(dsm8 + row * 80 + cc * 16) = *(const uint4*)(Qg + (size_t)row * 64 + cc * 16);
    }
    __syncthreads();

    unsigned qf[2][4];
    {
        const uint32_t qo = smQ + (uint32_t)((wid * 16 + lr) * 80 + lc * 16);
        ldm_x4(qf[0], qo);
        ldm_x4(qf[1], qo + 32);
    }

    float oacc[8][4] = {};
    float lsum0 = 0.f, lsum1 = 0.f;
    const float sc = 0.125f * 1.4426950408889634f / 16.0f;

    #pragma unroll
    for (int t = 0; t < 8; t++) {
        cp_wait<1>();
        __syncthreads();
        if (t + 2 < 8) load_kv(t + 2);
        cp_commit();

        const uint32_t kb = smK + (t % 3) * 5120;
        const uint32_t vb = smV + (t % 3) * 9216;

        #pragma unroll
        for (int p = 0; p < 4; p++) {
            float s0[4] = {}, s1[4] = {};
            #pragma unroll
            for (int ka = 0; ka < 2; ka++) {
                unsigned kf[4];
                ldm_x4(kf, kb + (p * 16 + lr) * 80 + lc * 16 + ka * 32);
                mma_f8(s0, qf[ka], kf[0], kf[2]);
                mma_f8(s1, qf[ka], kf[1], kf[3]);
            }
            #pragma unroll
            for (int i = 0; i < 4; i++) {
                float e0, e1;
                asm("ex2.approx.f32 %0, %1;" : "=f"(e0) : "f"(s0[i] * sc));
                asm("ex2.approx.f32 %0, %1;" : "=f"(e1) : "f"(s1[i] * sc));
                s0[i] = e0; s1[i] = e1;
            }
            lsum0 += s0[0] + s0[1] + s1[0] + s1[1];
            lsum1 += s0[2] + s0[3] + s1[2] + s1[3];

            unsigned pf[4];
            pf[0] = pk(s0[0], s0[1]);
            pf[1] = pk(s0[2], s0[3]);
            pf[2] = pk(s1[0], s1[1]);
            pf[3] = pk(s1[2], s1[3]);

            #pragma unroll
            for (int d = 0; d < 4; d++) {
                unsigned vf[4];
                ldm_x4_t(vf, vb + (p * 16 + lr) * 144 + lc * 16 + d * 32);
                mma16816(oacc[2 * d + 0], pf, vf[0], vf[1]);
                mma16816(oacc[2 * d + 1], pf, vf[2], vf[3]);
            }
        }
    }

    lsum0 += __shfl_xor_sync(0xffffffffu, lsum0, 1);
    lsum0 += __shfl_xor_sync(0xffffffffu, lsum0, 2);
    lsum1 += __shfl_xor_sync(0xffffffffu, lsum1, 1);
    lsum1 += __shfl_xor_sync(0xffffffffu, lsum1, 2);
    const float rs0 = 16.0f / lsum0, rs1 = 16.0f / lsum1;   // x16 fp8 prescale

    uint8_t* Og = g_xm8 + ((size_t)bt * 256 + qt * 128) * 512 + h * 64;
    const int r0 = wid * 16 + g;
    #pragma unroll
    for (int nb = 0; nb < 8; nb++) {
        int n = nb * 8 + t2;
        *(unsigned short*)&Og[(size_t)r0 * 512 + n] =
            pk8(oacc[nb][0] * rs0, oacc[nb][1] * rs0);
        *(unsigned short*)&Og[(size_t)(r0 + 8) * 512 + n] =
            pk8(oacc[nb][2] * rs1, oacc[nb][3] * rs1);
    }
}

// ---------------------------------------------------------------------------
extern "C" void kernel_launch(void* const* d_in, const int* in_sizes, int n_in,
                              void* d_out, int out_size)
{
    const float* q   = (const float*)d_in[0];
    const float* kv  = (const float*)d_in[1];
    const float* Wq  = (const float*)d_in[2];
    const float* bq  = (const float*)d_in[3];
    const float* Wkv = (const float*)d_in[4];
    const float* bkv = (const float*)d_in[5];
    const float* Wm  = (const float*)d_in[6];
    const float* bm  = (const float*)d_in[7];
    float* out = (float*)d_out;

    cudaFuncSetAttribute(proj_f8,    cudaFuncAttributeMaxDynamicSharedMemorySize, GSMEM);
    cudaFuncSetAttribute(out_f8,     cudaFuncAttributeMaxDynamicSharedMemorySize, GSMEM);
    cudaFuncSetAttribute(attn_mixed, cudaFuncAttributeMaxDynamicSharedMemorySize, ASMEM);

    convert_all<<<ALL8 / 256, 256>>>(q, kv, Wq, Wkv, Wm);

    proj_f8<<<2560, 256, GSMEM>>>(bq, bkv);
    attn_mixed<<<dim3(2, 8, 64), 256, ASMEM>>>();
    out_f8<<<dim3(4, 128), 256, GSMEM>>>(bm, q, out);
}